// round 1
// baseline (speedup 1.0000x reference)
#include <cuda_runtime.h>
#include <cstdint>
#include <cstdio>

// Problem constants (fixed shapes)
#define BQ_N 4096
#define NB 4
#define CC 128
#define KN 32
#define R1 5
#define S_TOT (NB * BQ_N)        // 16384 samples
#define S2_TOT (S_TOT * 4)       // 65536 (sample, r) columns
#define KCAT 416                 // 387 padded to multiple of 32
#define CONV_R2 0.04f            // (0.2)^2

// ---------------- scratch (device globals; no allocation allowed) ----------
__device__ float g_featT[S_TOT * CC];                    // (S, C) transpose of feat
__device__ float g_feat0[S_TOT * CC];                    // begin-conv output (S, C)
__device__ int   g_idx[S_TOT * KN];                      // ball-query neighbor indices
__device__ float g_wf[(size_t)S_TOT * R1 * CC];          // (S, R1*C)
__device__ float g_qf[S_TOT * CC];                       // (S, C)
__device__ float g_qf2[S_TOT * CC];                      // (S, C)
__device__ float g_cat[(size_t)S2_TOT * KCAT];           // (S2, 416)
__device__ float g_h[(size_t)S2_TOT * 256];              // (S2, 256)
__device__ float g_w1p[256 * KCAT];                      // zero-padded w_mlp1

// ---------------- transpose feat (B,C,N) -> featT (B,N,C) ------------------
__global__ void transpose_kernel(const float* __restrict__ feat,
                                 float* __restrict__ featT) {
    __shared__ float tile[32][33];
    int b = blockIdx.z;
    int n0 = blockIdx.x * 32, c0 = blockIdx.y * 32;
    int tx = threadIdx.x, ty = threadIdx.y;
#pragma unroll
    for (int i = ty; i < 32; i += 8)
        tile[i][tx] = feat[((size_t)(b * CC + c0 + i)) * BQ_N + n0 + tx];
    __syncthreads();
#pragma unroll
    for (int i = ty; i < 32; i += 8)
        featT[((size_t)(b * BQ_N + n0 + i)) * CC + c0 + tx] = tile[tx][i];
}

// ---------------- ball query: first 32 in-radius neighbors by index --------
__global__ void ballquery_kernel(const float* __restrict__ pos,
                                 int* __restrict__ idx) {
    __shared__ float sx[BQ_N], sy[BQ_N], sz[BQ_N];
    int b = blockIdx.y;
    const float* p = pos + (size_t)b * 3 * BQ_N;
    for (int i = threadIdx.x; i < BQ_N; i += blockDim.x) {
        sx[i] = p[i];
        sy[i] = p[BQ_N + i];
        sz[i] = p[2 * BQ_N + i];
    }
    __syncthreads();
    int warp = threadIdx.x >> 5, lane = threadIdx.x & 31;
    int n = blockIdx.x * (blockDim.x >> 5) + warp;
    float xn = sx[n], yn = sy[n], zn = sz[n];
    float nn = xn * xn + yn * yn + zn * zn;   // match ref: |p|^2 then expand
    int* out = idx + (size_t)(b * BQ_N + n) * KN;
    int count = 0;
    for (int m0 = 0; m0 < BQ_N && count < KN; m0 += 32) {
        int m = m0 + lane;
        float xm = sx[m], ym = sy[m], zm = sz[m];
        float nm = xm * xm + ym * ym + zm * zm;
        float dt = xn * xm + yn * ym + zn * zm;
        float sqd = (nn + nm) - 2.0f * dt;    // same expansion as reference
        bool ok = (sqd <= CONV_R2);           // kept unless sqd > r^2
        unsigned msk = __ballot_sync(0xffffffffu, ok);
        int p2 = count + __popc(msk & ((1u << lane) - 1u));
        if (ok && p2 < KN) out[p2] = m;
        count += __popc(msk);
        if (count > KN) count = KN;
    }
    for (int p2 = count + lane; p2 < KN; p2 += 32) out[p2] = BQ_N;
}

// ---------------- kernel-point correlation: wf (S, R1*C) -------------------
__global__ void kp_wf_kernel(const float* __restrict__ pos,
                             const int* __restrict__ idx,
                             const float* __restrict__ qp,      // (3,5) flat: qp[axis*5+r]
                             const float* __restrict__ feat0,   // (S, C)
                             float* __restrict__ wf) {
    int s = blockIdx.x;
    int b = s >> 12, n = s & (BQ_N - 1);
    int c = threadIdx.x;   // 128 threads = channels
    __shared__ float wsh[R1][KN];
    __shared__ int nidx[KN];
    if (c < KN) {
        int m = idx[(size_t)s * KN + c];
        nidx[c] = m;
        float wr[R1];
#pragma unroll
        for (int r = 0; r < R1; r++) wr[r] = 0.f;
        if (m < BQ_N) {
            const float* p = pos + (size_t)b * 3 * BQ_N;
            float rx = p[m] - p[n];
            float ry = p[BQ_N + m] - p[BQ_N + n];
            float rz = p[2 * BQ_N + m] - p[2 * BQ_N + n];
#pragma unroll
            for (int r = 0; r < R1; r++) {
                float dx = rx - qp[r];
                float dy = ry - qp[R1 + r];
                float dz = rz - qp[2 * R1 + r];
                float d = sqrtf(dx * dx + dy * dy + dz * dz);
                wr[r] = fmaxf(0.f, 1.f - d / 0.1f);
            }
        }
#pragma unroll
        for (int r = 0; r < R1; r++) wsh[r][c] = wr[r];
    }
    __syncthreads();
    float acc[R1] = {0.f, 0.f, 0.f, 0.f, 0.f};
#pragma unroll 4
    for (int k = 0; k < KN; k++) {
        int m = nidx[k];
        float f = (m < BQ_N) ? feat0[(size_t)(b * BQ_N + m) * CC + c] : 0.f;
#pragma unroll
        for (int r = 0; r < R1; r++) acc[r] += wsh[r][k] * f;
    }
#pragma unroll
    for (int r = 0; r < R1; r++)
        wf[(size_t)s * (R1 * CC) + r * CC + c] = acc[r];
}

// ---------------- build cat (S2, 416) --------------------------------------
__global__ void cat_kernel(const float* __restrict__ wf,
                           const float* __restrict__ qp,
                           const float* __restrict__ qf2,
                           const float* __restrict__ featT,
                           float* __restrict__ cat) {
    size_t id = (size_t)blockIdx.x * blockDim.x + threadIdx.x;
    const size_t total = (size_t)S2_TOT * KCAT;
    if (id >= total) return;
    int k = (int)(id % KCAT);
    size_t s2 = id / KCAT;
    int r = (int)(s2 & 3);
    size_t s = s2 >> 2;
    float v;
    if (k < 128)       v = wf[s * (R1 * CC) + (size_t)(r + 1) * CC + k];
    else if (k < 131)  v = qp[(k - 128) * R1 + (r + 1)];
    else if (k < 259)  v = qf2[s * CC + (k - 131)];
    else if (k < 387)  v = featT[s * CC + (k - 259)];
    else               v = 0.f;
    cat[id] = v;
}

// ---------------- pad w_mlp1 and emit the 12 query_pos outputs -------------
__global__ void prep_kernel(const float* __restrict__ w1,
                            const float* __restrict__ qp,
                            float* __restrict__ w1p,
                            float* __restrict__ out12) {
    int id = blockIdx.x * blockDim.x + threadIdx.x;
    if (id < 256 * KCAT) {
        int k = id % KCAT, o = id / KCAT;
        w1p[id] = (k < 387) ? w1[o * 387 + k] : 0.f;
    }
    if (id < 12) {
        int a = id >> 2, r = (id & 3) + 1;
        out12[id] = qp[a * R1 + r];
    }
}

// ---------------- tiled SGEMM: C[M,N] = epi(A[M,K] * B' + bias) -------------
// BT:    B stored (N,K) row-major (use B^T); else (K,N) row-major.
// RESID: add resid[M,N]; RELU: relu; PERM: scatter into (B,TD,N,R) layout.
template <bool BT, bool RELU, bool RESID, bool PERM>
__global__ void __launch_bounds__(256, 2)
sgemm_kernel(int M, int N, int K,
             const float* __restrict__ A, const float* __restrict__ B,
             const float* __restrict__ bias, const float* __restrict__ resid,
             float* __restrict__ C) {
    const int BM = 128, BN = 128, BK = 32;
    __shared__ float As[BK][BM + 4];
    __shared__ float Bs[BK][BN + 4];
    int tid = threadIdx.x;
    int tx = tid & 15, ty = tid >> 4;
    int m0 = blockIdx.y * BM, n0 = blockIdx.x * BN;
    float acc[8][8];
#pragma unroll
    for (int i = 0; i < 8; i++)
#pragma unroll
        for (int j = 0; j < 8; j++) acc[i][j] = 0.f;

    for (int k0 = 0; k0 < K; k0 += BK) {
#pragma unroll
        for (int it = 0; it < 4; it++) {   // A tile: 128x32, float4 along k
            int t = tid + it * 256;
            int m = t >> 3, k4 = (t & 7) << 2;
            float4 v = *(const float4*)(A + (size_t)(m0 + m) * K + k0 + k4);
            As[k4 + 0][m] = v.x; As[k4 + 1][m] = v.y;
            As[k4 + 2][m] = v.z; As[k4 + 3][m] = v.w;
        }
        if (BT) {
#pragma unroll
            for (int it = 0; it < 4; it++) {
                int t = tid + it * 256;
                int nn2 = t >> 3, k4 = (t & 7) << 2;
                float4 v = *(const float4*)(B + (size_t)(n0 + nn2) * K + k0 + k4);
                Bs[k4 + 0][nn2] = v.x; Bs[k4 + 1][nn2] = v.y;
                Bs[k4 + 2][nn2] = v.z; Bs[k4 + 3][nn2] = v.w;
            }
        } else {
#pragma unroll
            for (int it = 0; it < 4; it++) {
                int t = tid + it * 256;
                int kk2 = t >> 5, n4 = (t & 31) << 2;
                float4 v = *(const float4*)(B + (size_t)(k0 + kk2) * N + n0 + n4);
                *(float4*)&Bs[kk2][n4] = v;
            }
        }
        __syncthreads();
#pragma unroll
        for (int kk = 0; kk < BK; kk++) {
            float ra[8], rb[8];
            *(float4*)&ra[0] = *(const float4*)&As[kk][ty * 8];
            *(float4*)&ra[4] = *(const float4*)&As[kk][ty * 8 + 4];
            *(float4*)&rb[0] = *(const float4*)&Bs[kk][tx * 8];
            *(float4*)&rb[4] = *(const float4*)&Bs[kk][tx * 8 + 4];
#pragma unroll
            for (int i = 0; i < 8; i++)
#pragma unroll
                for (int j = 0; j < 8; j++) acc[i][j] += ra[i] * rb[j];
        }
        __syncthreads();
    }
#pragma unroll
    for (int i = 0; i < 8; i++) {
        int m = m0 + ty * 8 + i;
#pragma unroll
        for (int j = 0; j < 8; j++) {
            int nn2 = n0 + tx * 8 + j;
            float v = acc[i][j] + bias[nn2];
            if (RESID) v += resid[(size_t)m * N + nn2];
            if (RELU) v = fmaxf(v, 0.f);
            if (PERM) {
                // m = (b*4096+n)*4+r ; out idx = ((b*128+d)*4096+n)*4+r
                int bb = m >> 14;
                size_t addr = ((size_t)(bb * 128 + nn2) << 14) + (size_t)(m & 16383);
                C[addr] = v;
            } else {
                C[(size_t)m * N + nn2] = v;
            }
        }
    }
}

// ---------------- launch ----------------------------------------------------
extern "C" void kernel_launch(void* const* d_in, const int* in_sizes, int n_in,
                              void* d_out, int out_size) {
    (void)in_sizes; (void)n_in; (void)out_size;
    const float* pos       = (const float*)d_in[0];
    const float* feat      = (const float*)d_in[1];
    const float* qp        = (const float*)d_in[2];
    const float* w_begin   = (const float*)d_in[3];
    const float* b_begin   = (const float*)d_in[4];
    const float* kp_weight = (const float*)d_in[5];
    const float* kp_bias   = (const float*)d_in[6];
    const float* w_end     = (const float*)d_in[7];
    const float* b_end     = (const float*)d_in[8];
    const float* w_mlp1    = (const float*)d_in[9];
    const float* b_mlp1    = (const float*)d_in[10];
    const float* w_mlp2    = (const float*)d_in[11];
    const float* b_mlp2    = (const float*)d_in[12];
    float* out = (float*)d_out;

    float *featT, *feat0, *wf, *qf, *qf2, *cat, *h, *w1p;
    int* idx;
    cudaGetSymbolAddress((void**)&featT, g_featT);
    cudaGetSymbolAddress((void**)&feat0, g_feat0);
    cudaGetSymbolAddress((void**)&idx,   g_idx);
    cudaGetSymbolAddress((void**)&wf,    g_wf);
    cudaGetSymbolAddress((void**)&qf,    g_qf);
    cudaGetSymbolAddress((void**)&qf2,   g_qf2);
    cudaGetSymbolAddress((void**)&cat,   g_cat);
    cudaGetSymbolAddress((void**)&h,     g_h);
    cudaGetSymbolAddress((void**)&w1p,   g_w1p);

    // Stage 0: transpose + ball query + weight pad + the 12 qp outputs
    transpose_kernel<<<dim3(128, 4, 4), dim3(32, 8)>>>(feat, featT);
    ballquery_kernel<<<dim3(512, 4), 256>>>(pos, idx);
    prep_kernel<<<(256 * KCAT + 255) / 256, 256>>>(w_mlp1, qp, w1p, out);

    // feat0 = featT @ w_begin^T + b_begin        (no relu)
    sgemm_kernel<true, false, false, false><<<dim3(1, 128), 256>>>(
        S_TOT, 128, 128, featT, w_begin, b_begin, nullptr, feat0);

    // kernel-point correlation -> wf (S, 640)
    kp_wf_kernel<<<S_TOT, 128>>>(pos, idx, qp, feat0, wf);

    // qf = relu(wf @ kp_weight + kp_bias)        (kp_weight is (640,128) row-major)
    sgemm_kernel<false, true, false, false><<<dim3(1, 128), 256>>>(
        S_TOT, 128, 640, wf, kp_weight, kp_bias, nullptr, qf);

    // qf2 = relu(qf @ w_end^T + b_end + featT)
    sgemm_kernel<true, true, true, false><<<dim3(1, 128), 256>>>(
        S_TOT, 128, 128, qf, w_end, b_end, featT, qf2);

    // cat (S2, 416)
    {
        size_t total = (size_t)S2_TOT * KCAT;
        cat_kernel<<<(unsigned)((total + 255) / 256), 256>>>(wf, qp, qf2, featT, cat);
    }

    // h = relu(cat @ w1p^T + b_mlp1)
    sgemm_kernel<true, true, false, false><<<dim3(2, 512), 256>>>(
        S2_TOT, 256, KCAT, cat, w1p, b_mlp1, nullptr, h);

    // queries = relu(h @ w_mlp2^T + b_mlp2), scattered to (B, TD, N, R)
    sgemm_kernel<true, true, false, true><<<dim3(1, 512), 256>>>(
        S2_TOT, 128, 256, h, w_mlp2, b_mlp2, nullptr, out + 12);
}

// round 4
// speedup vs baseline: 1.5097x; 1.5097x over previous
#include <cuda_runtime.h>
#include <cstdint>

// Problem constants (fixed shapes)
#define BQ_N 4096
#define NB 4
#define CC 128
#define KN 32
#define R1 5
#define S_TOT (NB * BQ_N)        // 16384 samples
#define S2_TOT (S_TOT * 4)       // 65536 (sample, r) columns
#define KCAT 416                 // 387 padded to multiple of 32
#define CONV_R2 0.04f            // (0.2)^2

// ---------------- scratch (device globals; no allocation allowed) ----------
__device__ float g_featT[S_TOT * CC];
__device__ float g_feat0[S_TOT * CC];
__device__ int   g_idx[S_TOT * KN];
__device__ float g_wf[(size_t)S_TOT * R1 * CC];
__device__ float g_qf[S_TOT * CC];
__device__ float g_qf2[S_TOT * CC];
__device__ float g_cat[(size_t)S2_TOT * KCAT];
__device__ float g_h[(size_t)S2_TOT * 256];
__device__ float g_w1p[256 * KCAT];
__device__ float g_kpT[CC * (R1 * CC)];   // kp_weight transposed: (128, 640)

__device__ __forceinline__ uint32_t smem_u32(const void* p) {
    uint32_t a;
    asm("{ .reg .u64 t; cvta.to.shared.u64 t, %1; cvt.u32.u64 %0, t; }"
        : "=r"(a) : "l"(p));
    return a;
}

#define MMA_TF32(d, a0, a1, a2, a3, b0, b1) \
    asm volatile( \
        "mma.sync.aligned.m16n8k8.row.col.f32.tf32.tf32.f32 " \
        "{%0,%1,%2,%3}, {%4,%5,%6,%7}, {%8,%9}, {%0,%1,%2,%3};" \
        : "+f"((d)[0]), "+f"((d)[1]), "+f"((d)[2]), "+f"((d)[3]) \
        : "r"(a0), "r"(a1), "r"(a2), "r"(a3), "r"(b0), "r"(b1))

// ---------------- 3xTF32 mma.sync GEMM ------------------------------------
// C[M, Ng-tile] = epi(A @ B^T + bias), fp32-accurate via hi/lo tf32 split.
// A: (M, K) row-major f32.  B: (N, K) row-major f32.  M,N mult of 128, K mult of 32.
// Tile: BM=128, BN=128, BK=32. 8 warps (4 in m, 2 in n), warp tile 32x64.
template <bool RELU, bool RESID, bool PERM>
__global__ void __launch_bounds__(256, 2)
mma_gemm(int M, int Ng, int K,
         const float* __restrict__ A, const float* __restrict__ B,
         const float* __restrict__ bias, const float* __restrict__ resid,
         float* __restrict__ C) {
    extern __shared__ float sm[];   // 2 stages x (As 128*36 + Bs 128*36)
    const int SSTRIDE = 9216;       // floats per stage
    int tid = threadIdx.x;
    int lane = tid & 31, wid = tid >> 5;
    int wm = wid & 3, wn = wid >> 2;
    int m0 = blockIdx.y << 7, n0 = blockIdx.x << 7;
    int nK = K >> 5;

    float acc[2][8][4];
#pragma unroll
    for (int mi = 0; mi < 2; mi++)
#pragma unroll
        for (int ni = 0; ni < 8; ni++)
#pragma unroll
            for (int u = 0; u < 4; u++) acc[mi][ni][u] = 0.f;

    auto load_tile = [&](int kt) {
        int s = kt & 1;
        const float* Ag = A + (size_t)m0 * K + ((size_t)kt << 5);
        const float* Bg = B + (size_t)n0 * K + ((size_t)kt << 5);
        float* dst = sm + s * SSTRIDE;
#pragma unroll
        for (int i = 0; i < 4; i++) {
            int c = tid + (i << 8);
            int row = c >> 3, j = c & 7;
            uint32_t sa = smem_u32(dst + row * 36 + j * 4);
            asm volatile("cp.async.cg.shared.global [%0], [%1], 16;"
                         :: "r"(sa), "l"(Ag + (size_t)row * K + j * 4) : "memory");
        }
#pragma unroll
        for (int i = 0; i < 4; i++) {
            int c = tid + (i << 8);
            int row = c >> 3, j = c & 7;
            uint32_t sa = smem_u32(dst + 4608 + row * 36 + j * 4);
            asm volatile("cp.async.cg.shared.global [%0], [%1], 16;"
                         :: "r"(sa), "l"(Bg + (size_t)row * K + j * 4) : "memory");
        }
        asm volatile("cp.async.commit_group;" ::: "memory");
    };

    load_tile(0);
    int arow = wm * 32 + (lane >> 2);
    int brow = wn * 64 + (lane >> 2);
    int kc = lane & 3;

    for (int kt = 0; kt < nK; kt++) {
        if (kt + 1 < nK) {
            load_tile(kt + 1);
            asm volatile("cp.async.wait_group 1;" ::: "memory");
        } else {
            asm volatile("cp.async.wait_group 0;" ::: "memory");
        }
        __syncthreads();
        const float* Asb = sm + (kt & 1) * SSTRIDE;
        const float* Bsb = Asb + 4608;
#pragma unroll
        for (int ks = 0; ks < 4; ks++) {
            int kk = ks * 8 + kc;
            uint32_t ah[2][4], al[2][4];
#pragma unroll
            for (int mi = 0; mi < 2; mi++) {
                const float* p = Asb + (arow + mi * 16) * 36 + kk;
                float vv[4];
                vv[0] = p[0];
                vv[1] = p[8 * 36];
                vv[2] = p[4];
                vv[3] = p[8 * 36 + 4];
#pragma unroll
                for (int u = 0; u < 4; u++) {
                    uint32_t hi = __float_as_uint(vv[u]) & 0xFFFFE000u;
                    ah[mi][u] = hi;
                    al[mi][u] = __float_as_uint(vv[u] - __uint_as_float(hi));
                }
            }
#pragma unroll
            for (int ni = 0; ni < 8; ni++) {
                const float* q = Bsb + (brow + ni * 8) * 36 + kk;
                float w0 = q[0], w1 = q[4];
                uint32_t bh0 = __float_as_uint(w0) & 0xFFFFE000u;
                uint32_t bl0 = __float_as_uint(w0 - __uint_as_float(bh0));
                uint32_t bh1 = __float_as_uint(w1) & 0xFFFFE000u;
                uint32_t bl1 = __float_as_uint(w1 - __uint_as_float(bh1));
#pragma unroll
                for (int mi = 0; mi < 2; mi++) {
                    MMA_TF32(acc[mi][ni], al[mi][0], al[mi][1], al[mi][2], al[mi][3], bh0, bh1);
                    MMA_TF32(acc[mi][ni], ah[mi][0], ah[mi][1], ah[mi][2], ah[mi][3], bl0, bl1);
                    MMA_TF32(acc[mi][ni], ah[mi][0], ah[mi][1], ah[mi][2], ah[mi][3], bh0, bh1);
                }
            }
        }
        __syncthreads();
    }

    // Epilogue. c0:(g,2t) c1:(g,2t+1) c2:(g+8,2t) c3:(g+8,2t+1)
    int mrow = m0 + wm * 32 + (lane >> 2);
    int nc0 = n0 + wn * 64 + 2 * (lane & 3);
#pragma unroll
    for (int ni = 0; ni < 8; ni++) {
        int n = nc0 + ni * 8;
        float bv0 = bias[n], bv1 = bias[n + 1];
#pragma unroll
        for (int mi = 0; mi < 2; mi++) {
#pragma unroll
            for (int h2 = 0; h2 < 2; h2++) {
                int m = mrow + mi * 16 + h2 * 8;
                float x0 = acc[mi][ni][2 * h2]     + bv0;
                float x1 = acc[mi][ni][2 * h2 + 1] + bv1;
                if (RESID) {
                    x0 += resid[(size_t)m * Ng + n];
                    x1 += resid[(size_t)m * Ng + n + 1];
                }
                if (RELU) { x0 = fmaxf(x0, 0.f); x1 = fmaxf(x1, 0.f); }
                if (PERM) {
                    // m = (b*4096+pt)*4+r ; out idx = ((b*128+d)*4096+pt)*4+r
                    int bb = m >> 14;
                    size_t low = (size_t)(m & 16383);
                    C[(((size_t)(bb * 128 + n)) << 14) + low] = x0;
                    C[(((size_t)(bb * 128 + n + 1)) << 14) + low] = x1;
                } else {
                    *(float2*)(C + (size_t)m * Ng + n) = make_float2(x0, x1);
                }
            }
        }
    }
}

// ---------------- transpose feat (B,C,N) -> featT (B,N,C) ------------------
__global__ void transpose_kernel(const float* __restrict__ feat,
                                 float* __restrict__ featT) {
    __shared__ float tile[32][33];
    int b = blockIdx.z;
    int n0 = blockIdx.x * 32, c0 = blockIdx.y * 32;
    int tx = threadIdx.x, ty = threadIdx.y;
#pragma unroll
    for (int i = ty; i < 32; i += 8)
        tile[i][tx] = feat[((size_t)(b * CC + c0 + i)) * BQ_N + n0 + tx];
    __syncthreads();
#pragma unroll
    for (int i = ty; i < 32; i += 8)
        featT[((size_t)(b * BQ_N + n0 + i)) * CC + c0 + tx] = tile[tx][i];
}

// ---------------- ball query: first 32 in-radius neighbors by index --------
__global__ void ballquery_kernel(const float* __restrict__ pos,
                                 int* __restrict__ idx) {
    __shared__ float sx[BQ_N], sy[BQ_N], sz[BQ_N];
    int b = blockIdx.y;
    const float* p = pos + (size_t)b * 3 * BQ_N;
    for (int i = threadIdx.x; i < BQ_N; i += blockDim.x) {
        sx[i] = p[i];
        sy[i] = p[BQ_N + i];
        sz[i] = p[2 * BQ_N + i];
    }
    __syncthreads();
    int warp = threadIdx.x >> 5, lane = threadIdx.x & 31;
    int n = blockIdx.x * (blockDim.x >> 5) + warp;
    float xn = sx[n], yn = sy[n], zn = sz[n];
    float nn = xn * xn + yn * yn + zn * zn;
    int* out = idx + (size_t)(b * BQ_N + n) * KN;
    int count = 0;
    for (int m0 = 0; m0 < BQ_N && count < KN; m0 += 32) {
        int m = m0 + lane;
        float xm = sx[m], ym = sy[m], zm = sz[m];
        float nm = xm * xm + ym * ym + zm * zm;
        float dt = xn * xm + yn * ym + zn * zm;
        float sqd = (nn + nm) - 2.0f * dt;
        bool ok = (sqd <= CONV_R2);
        unsigned msk = __ballot_sync(0xffffffffu, ok);
        int p2 = count + __popc(msk & ((1u << lane) - 1u));
        if (ok && p2 < KN) out[p2] = m;
        count += __popc(msk);
        if (count > KN) count = KN;
    }
    for (int p2 = count + lane; p2 < KN; p2 += 32) out[p2] = BQ_N;
}

// ---------------- kernel-point correlation: wf (S, R1*C) -------------------
__global__ void kp_wf_kernel(const float* __restrict__ pos,
                             const int* __restrict__ idx,
                             const float* __restrict__ qp,
                             const float* __restrict__ feat0,
                             float* __restrict__ wf) {
    int s = blockIdx.x;
    int b = s >> 12, n = s & (BQ_N - 1);
    int c = threadIdx.x;
    __shared__ float wsh[R1][KN];
    __shared__ int nidx[KN];
    if (c < KN) {
        int m = idx[(size_t)s * KN + c];
        nidx[c] = m;
        float wr[R1];
#pragma unroll
        for (int r = 0; r < R1; r++) wr[r] = 0.f;
        if (m < BQ_N) {
            const float* p = pos + (size_t)b * 3 * BQ_N;
            float rx = p[m] - p[n];
            float ry = p[BQ_N + m] - p[BQ_N + n];
            float rz = p[2 * BQ_N + m] - p[2 * BQ_N + n];
#pragma unroll
            for (int r = 0; r < R1; r++) {
                float dx = rx - qp[r];
                float dy = ry - qp[R1 + r];
                float dz = rz - qp[2 * R1 + r];
                float d = sqrtf(dx * dx + dy * dy + dz * dz);
                wr[r] = fmaxf(0.f, 1.f - d / 0.1f);
            }
        }
#pragma unroll
        for (int r = 0; r < R1; r++) wsh[r][c] = wr[r];
    }
    __syncthreads();
    float acc[R1] = {0.f, 0.f, 0.f, 0.f, 0.f};
#pragma unroll 4
    for (int k = 0; k < KN; k++) {
        int m = nidx[k];
        float f = (m < BQ_N) ? feat0[(size_t)(b * BQ_N + m) * CC + c] : 0.f;
#pragma unroll
        for (int r = 0; r < R1; r++) acc[r] += wsh[r][k] * f;
    }
#pragma unroll
    for (int r = 0; r < R1; r++)
        wf[(size_t)s * (R1 * CC) + r * CC + c] = acc[r];
}

// ---------------- build cat (S2, 416) --------------------------------------
__global__ void cat_kernel(const float* __restrict__ wf,
                           const float* __restrict__ qp,
                           const float* __restrict__ qf2,
                           const float* __restrict__ featT,
                           float* __restrict__ cat) {
    size_t id = (size_t)blockIdx.x * blockDim.x + threadIdx.x;
    const size_t total = (size_t)S2_TOT * KCAT;
    if (id >= total) return;
    int k = (int)(id % KCAT);
    size_t s2 = id / KCAT;
    int r = (int)(s2 & 3);
    size_t s = s2 >> 2;
    float v;
    if (k < 128)       v = wf[s * (R1 * CC) + (size_t)(r + 1) * CC + k];
    else if (k < 131)  v = qp[(k - 128) * R1 + (r + 1)];
    else if (k < 259)  v = qf2[s * CC + (k - 131)];
    else if (k < 387)  v = featT[s * CC + (k - 259)];
    else               v = 0.f;
    cat[id] = v;
}

// ---- pad w_mlp1, transpose kp_weight, emit the 12 query_pos outputs -------
__global__ void prep_kernel(const float* __restrict__ w1,
                            const float* __restrict__ qp,
                            const float* __restrict__ kpw,
                            float* __restrict__ w1p,
                            float* __restrict__ kpT,
                            float* __restrict__ out12) {
    int id = blockIdx.x * blockDim.x + threadIdx.x;
    if (id < 256 * KCAT) {
        int k = id % KCAT, o = id / KCAT;
        w1p[id] = (k < 387) ? w1[o * 387 + k] : 0.f;
    }
    if (id < 128 * 640) {
        int d = id / 640, k = id % 640;
        kpT[id] = kpw[k * 128 + d];
    }
    if (id < 12) {
        int a = id >> 2, r = (id & 3) + 1;
        out12[id] = qp[a * R1 + r];
    }
}

// ---------------- launch ----------------------------------------------------
extern "C" void kernel_launch(void* const* d_in, const int* in_sizes, int n_in,
                              void* d_out, int out_size) {
    (void)in_sizes; (void)n_in; (void)out_size;
    const float* pos       = (const float*)d_in[0];
    const float* feat      = (const float*)d_in[1];
    const float* qp        = (const float*)d_in[2];
    const float* w_begin   = (const float*)d_in[3];
    const float* b_begin   = (const float*)d_in[4];
    const float* kp_weight = (const float*)d_in[5];
    const float* kp_bias   = (const float*)d_in[6];
    const float* w_end     = (const float*)d_in[7];
    const float* b_end     = (const float*)d_in[8];
    const float* w_mlp1    = (const float*)d_in[9];
    const float* b_mlp1    = (const float*)d_in[10];
    const float* w_mlp2    = (const float*)d_in[11];
    const float* b_mlp2    = (const float*)d_in[12];
    float* out = (float*)d_out;

    float *featT, *feat0, *wf, *qf, *qf2, *cat, *h, *w1p, *kpT;
    int* idx;
    cudaGetSymbolAddress((void**)&featT, g_featT);
    cudaGetSymbolAddress((void**)&feat0, g_feat0);
    cudaGetSymbolAddress((void**)&idx,   g_idx);
    cudaGetSymbolAddress((void**)&wf,    g_wf);
    cudaGetSymbolAddress((void**)&qf,    g_qf);
    cudaGetSymbolAddress((void**)&qf2,   g_qf2);
    cudaGetSymbolAddress((void**)&cat,   g_cat);
    cudaGetSymbolAddress((void**)&h,     g_h);
    cudaGetSymbolAddress((void**)&w1p,   g_w1p);
    cudaGetSymbolAddress((void**)&kpT,   g_kpT);

    const int SMEM_DYN = 2 * 9216 * 4;   // 73728 B
    cudaFuncSetAttribute(mma_gemm<false, false, false>,
                         cudaFuncAttributeMaxDynamicSharedMemorySize, SMEM_DYN);
    cudaFuncSetAttribute(mma_gemm<true, false, false>,
                         cudaFuncAttributeMaxDynamicSharedMemorySize, SMEM_DYN);
    cudaFuncSetAttribute(mma_gemm<true, true, false>,
                         cudaFuncAttributeMaxDynamicSharedMemorySize, SMEM_DYN);
    cudaFuncSetAttribute(mma_gemm<true, false, true>,
                         cudaFuncAttributeMaxDynamicSharedMemorySize, SMEM_DYN);

    // Stage 0: transpose + ball query + prep
    transpose_kernel<<<dim3(128, 4, 4), dim3(32, 8)>>>(feat, featT);
    ballquery_kernel<<<dim3(512, 4), 256>>>(pos, idx);
    prep_kernel<<<(256 * KCAT + 255) / 256, 256>>>(w_mlp1, qp, kp_weight, w1p, kpT, out);

    // feat0 = featT @ w_begin^T + b_begin
    mma_gemm<false, false, false><<<dim3(1, 128), 256, SMEM_DYN>>>(
        S_TOT, 128, 128, featT, w_begin, b_begin, nullptr, feat0);

    // kernel-point correlation -> wf (S, 640)
    kp_wf_kernel<<<S_TOT, 128>>>(pos, idx, qp, feat0, wf);

    // qf = relu(wf @ kpT^T + kp_bias)
    mma_gemm<true, false, false><<<dim3(1, 128), 256, SMEM_DYN>>>(
        S_TOT, 128, 640, wf, kpT, kp_bias, nullptr, qf);

    // qf2 = relu(qf @ w_end^T + b_end + featT)
    mma_gemm<true, true, false><<<dim3(1, 128), 256, SMEM_DYN>>>(
        S_TOT, 128, 128, qf, w_end, b_end, featT, qf2);

    // cat (S2, 416)
    {
        size_t total = (size_t)S2_TOT * KCAT;
        cat_kernel<<<(unsigned)((total + 255) / 256), 256>>>(wf, qp, qf2, featT, cat);
    }

    // h = relu(cat @ w1p^T + b_mlp1)
    mma_gemm<true, false, false><<<dim3(2, 512), 256, SMEM_DYN>>>(
        S2_TOT, 256, KCAT, cat, w1p, b_mlp1, nullptr, h);

    // queries = relu(h @ w_mlp2^T + b_mlp2), scattered to (B, TD, N, R)
    mma_gemm<true, false, true><<<dim3(1, 512), 256, SMEM_DYN>>>(
        S2_TOT, 128, 256, h, w_mlp2, b_mlp2, nullptr, out + 12);
}

// round 5
// speedup vs baseline: 1.9669x; 1.3029x over previous
#include <cuda_runtime.h>
#include <cstdint>

// Problem constants (fixed shapes)
#define BQ_N 4096
#define NB 4
#define CC 128
#define KN 32
#define R1 5
#define S_TOT (NB * BQ_N)        // 16384 samples
#define S2_TOT (S_TOT * 4)       // 65536 (sample, r) columns
#define CONV_R2 0.04f            // (0.2)^2

// ---------------- scratch (device globals; no allocation allowed) ----------
__device__ float g_featT[S_TOT * CC];
__device__ float g_feat0[S_TOT * CC];
__device__ int   g_idx[S_TOT * KN];
__device__ float g_wf[(size_t)S_TOT * R1 * CC];
__device__ float g_qf[S_TOT * CC];
__device__ float g_qf2[S_TOT * CC];
__device__ float g_Y[(size_t)S_TOT * 256];
__device__ float g_h[(size_t)S2_TOT * 256];
// pre-split weights, interleaved (N, 2K): [2k]=hi, [2k+1]=lo
__device__ float g_wbs[128 * 256];     // w_begin  (128,128)
__device__ float g_kpTs[128 * 1280];   // kp_weight^T (128,640)
__device__ float g_wes[128 * 256];     // w_end    (128,128)
__device__ float g_w1as[256 * 256];    // w_mlp1 cols 0..127   (256,128)
__device__ float g_w1cds[256 * 512];   // w_mlp1 cols 131..386 (256,256)
__device__ float g_m2s[128 * 512];     // w_mlp2   (128,256)
__device__ float g_bias2d[4 * 256];    // per-r qp contribution to mlp1

__device__ __forceinline__ uint32_t smem_u32(const void* p) {
    uint32_t a;
    asm("{ .reg .u64 t; cvta.to.shared.u64 t, %1; cvt.u32.u64 %0, t; }"
        : "=r"(a) : "l"(p));
    return a;
}

#define MMA_TF32(d, a0, a1, a2, a3, b0, b1) \
    asm volatile( \
        "mma.sync.aligned.m16n8k8.row.col.f32.tf32.tf32.f32 " \
        "{%0,%1,%2,%3}, {%4,%5,%6,%7}, {%8,%9}, {%0,%1,%2,%3};" \
        : "+f"((d)[0]), "+f"((d)[1]), "+f"((d)[2]), "+f"((d)[3]) \
        : "r"(a0), "r"(a1), "r"(a2), "r"(a3), "r"(b0), "r"(b1))

// ---------------- 3xTF32 mma.sync GEMM, pre-split B -------------------------
// C[M, 128-tile of Ng] = epi(A @ B^T + bias); fp32-accurate hi/lo products.
// Bs: (N, 2K) interleaved hi/lo, row-major.
// AMODE 0: A row-major (M,K).
// AMODE 1: row m -> s=m>>2, r=m&3; A-row = wf + s*640 + (r+1)*128 (K=128).
// AMODE 2: row m = s; kt<4 from A (s,128), kt>=4 from A2 (s,128) (K=256).
// Smem/stage: A 128x36 f, B 128x72 f (stride 72 = conflict-free LDS.64).
template <int AMODE, bool RELU, bool RESID, bool RBCAST, bool BIAS2D, bool PERM>
__global__ void __launch_bounds__(256, 2)
mma_gemm(int M, int Ng, int K,
         const float* __restrict__ A, const float* __restrict__ A2,
         const float* __restrict__ Bs,
         const float* __restrict__ bias, const float* __restrict__ resid,
         float* __restrict__ C) {
    extern __shared__ float sm[];
    const int SSTRIDE = 13824;          // floats per stage (4608 A + 9216 B)
    int tid = threadIdx.x;
    int lane = tid & 31, wid = tid >> 5;
    int wm = wid & 3, wn = wid >> 2;
    int m0 = blockIdx.y << 7, n0 = blockIdx.x << 7;
    int nK = K >> 5;

    float acc[2][8][4];
#pragma unroll
    for (int mi = 0; mi < 2; mi++)
#pragma unroll
        for (int ni = 0; ni < 8; ni++)
#pragma unroll
            for (int u = 0; u < 4; u++) acc[mi][ni][u] = 0.f;

    auto load_tile = [&](int kt) {
        float* dst = sm + (kt & 1) * SSTRIDE;
#pragma unroll
        for (int i = 0; i < 4; i++) {              // A tile 128x32
            int c = tid + (i << 8);
            int row = c >> 3, j = c & 7;
            int m = m0 + row;
            const float* g;
            if (AMODE == 0) {
                g = A + (size_t)m * K + (kt << 5) + (j << 2);
            } else if (AMODE == 1) {
                int s = m >> 2, r = m & 3;
                g = A + (size_t)s * 640 + ((r + 1) << 7) + (kt << 5) + (j << 2);
            } else {
                const float* base = (kt < 4) ? A : A2;
                int k2 = (kt < 4) ? kt : (kt - 4);
                g = base + ((size_t)m << 7) + (k2 << 5) + (j << 2);
            }
            uint32_t sa = smem_u32(dst + row * 36 + (j << 2));
            asm volatile("cp.async.cg.shared.global [%0], [%1], 16;"
                         :: "r"(sa), "l"(g) : "memory");
        }
#pragma unroll
        for (int i = 0; i < 8; i++) {              // B tile 128 x 64 (hi/lo)
            int c = tid + (i << 8);
            int row = c >> 4, ch = c & 15;
            const float* g = Bs + (size_t)(n0 + row) * (2 * K) + (kt << 6) + (ch << 2);
            uint32_t sa = smem_u32(dst + 4608 + row * 72 + (ch << 2));
            asm volatile("cp.async.cg.shared.global [%0], [%1], 16;"
                         :: "r"(sa), "l"(g) : "memory");
        }
        asm volatile("cp.async.commit_group;" ::: "memory");
    };

    load_tile(0);
    int arow = wm * 32 + (lane >> 2);
    int brow = wn * 64 + (lane >> 2);
    int kc = lane & 3;

    for (int kt = 0; kt < nK; kt++) {
        if (kt + 1 < nK) {
            load_tile(kt + 1);
            asm volatile("cp.async.wait_group 1;" ::: "memory");
        } else {
            asm volatile("cp.async.wait_group 0;" ::: "memory");
        }
        __syncthreads();
        const float* Asb = sm + (kt & 1) * SSTRIDE;
        const float* Bsb = Asb + 4608;
#pragma unroll
        for (int ks = 0; ks < 4; ks++) {
            int kk = ks * 8 + kc;
            uint32_t ah[2][4], al[2][4];
#pragma unroll
            for (int mi = 0; mi < 2; mi++) {
                const float* p = Asb + (arow + mi * 16) * 36 + kk;
                float vv[4];
                vv[0] = p[0];
                vv[1] = p[8 * 36];
                vv[2] = p[4];
                vv[3] = p[8 * 36 + 4];
#pragma unroll
                for (int u = 0; u < 4; u++) {
                    uint32_t hi = __float_as_uint(vv[u]) & 0xFFFFE000u;
                    ah[mi][u] = hi;
                    al[mi][u] = __float_as_uint(vv[u] - __uint_as_float(hi));
                }
            }
#pragma unroll
            for (int ni = 0; ni < 8; ni++) {
                const float2* q = (const float2*)(Bsb + (brow + ni * 8) * 72 + 2 * kk);
                float2 p0 = q[0];        // (hi, lo) at k = kk
                float2 p1 = q[4];        // (hi, lo) at k = kk+4
                uint32_t bh0 = __float_as_uint(p0.x), bl0 = __float_as_uint(p0.y);
                uint32_t bh1 = __float_as_uint(p1.x), bl1 = __float_as_uint(p1.y);
#pragma unroll
                for (int mi = 0; mi < 2; mi++) {
                    MMA_TF32(acc[mi][ni], al[mi][0], al[mi][1], al[mi][2], al[mi][3], bh0, bh1);
                    MMA_TF32(acc[mi][ni], ah[mi][0], ah[mi][1], ah[mi][2], ah[mi][3], bl0, bl1);
                    MMA_TF32(acc[mi][ni], ah[mi][0], ah[mi][1], ah[mi][2], ah[mi][3], bh0, bh1);
                }
            }
        }
        __syncthreads();
    }

    // Epilogue. c0:(g,2t) c1:(g,2t+1) c2:(g+8,2t) c3:(g+8,2t+1)
    int mrow = m0 + wm * 32 + (lane >> 2);
    int rsel = mrow & 3;                 // constant across mi/h2 (offsets mult of 8)
    int nc0 = n0 + wn * 64 + 2 * (lane & 3);
#pragma unroll
    for (int ni = 0; ni < 8; ni++) {
        int n = nc0 + ni * 8;
        int boff = BIAS2D ? rsel * Ng : 0;
        float bv0 = bias[boff + n], bv1 = bias[boff + n + 1];
#pragma unroll
        for (int mi = 0; mi < 2; mi++) {
#pragma unroll
            for (int h2 = 0; h2 < 2; h2++) {
                int m = mrow + mi * 16 + h2 * 8;
                float x0 = acc[mi][ni][2 * h2]     + bv0;
                float x1 = acc[mi][ni][2 * h2 + 1] + bv1;
                if (RESID) {
                    size_t rr = RBCAST ? ((size_t)(m >> 2) * Ng + n)
                                       : ((size_t)m * Ng + n);
                    x0 += resid[rr];
                    x1 += resid[rr + 1];
                }
                if (RELU) { x0 = fmaxf(x0, 0.f); x1 = fmaxf(x1, 0.f); }
                if (PERM) {
                    // m = (b*4096+pt)*4+r ; out idx = ((b*128+d)*4096+pt)*4+r
                    int bb = m >> 14;
                    size_t low = (size_t)(m & 16383);
                    C[(((size_t)(bb * 128 + n)) << 14) + low] = x0;
                    C[(((size_t)(bb * 128 + n + 1)) << 14) + low] = x1;
                } else {
                    *(float2*)(C + (size_t)m * Ng + n) = make_float2(x0, x1);
                }
            }
        }
    }
}

// ---------------- transpose feat (B,C,N) -> featT (B,N,C) ------------------
__global__ void transpose_kernel(const float* __restrict__ feat,
                                 float* __restrict__ featT) {
    __shared__ float tile[32][33];
    int b = blockIdx.z;
    int n0 = blockIdx.x * 32, c0 = blockIdx.y * 32;
    int tx = threadIdx.x, ty = threadIdx.y;
#pragma unroll
    for (int i = ty; i < 32; i += 8)
        tile[i][tx] = feat[((size_t)(b * CC + c0 + i)) * BQ_N + n0 + tx];
    __syncthreads();
#pragma unroll
    for (int i = ty; i < 32; i += 8)
        featT[((size_t)(b * BQ_N + n0 + i)) * CC + c0 + tx] = tile[tx][i];
}

// ---------------- ball query: first 32 in-radius neighbors by index --------
__global__ void ballquery_kernel(const float* __restrict__ pos,
                                 int* __restrict__ idx) {
    __shared__ float sx[BQ_N], sy[BQ_N], sz[BQ_N];
    int b = blockIdx.y;
    const float* p = pos + (size_t)b * 3 * BQ_N;
    for (int i = threadIdx.x; i < BQ_N; i += blockDim.x) {
        sx[i] = p[i];
        sy[i] = p[BQ_N + i];
        sz[i] = p[2 * BQ_N + i];
    }
    __syncthreads();
    int warp = threadIdx.x >> 5, lane = threadIdx.x & 31;
    int n = blockIdx.x * (blockDim.x >> 5) + warp;
    float xn = sx[n], yn = sy[n], zn = sz[n];
    float nn = xn * xn + yn * yn + zn * zn;
    int* out = idx + (size_t)(b * BQ_N + n) * KN;
    int count = 0;
    for (int m0 = 0; m0 < BQ_N && count < KN; m0 += 32) {
        int m = m0 + lane;
        float xm = sx[m], ym = sy[m], zm = sz[m];
        float nm = xm * xm + ym * ym + zm * zm;
        float dt = xn * xm + yn * ym + zn * zm;
        float sqd = (nn + nm) - 2.0f * dt;
        bool ok = (sqd <= CONV_R2);
        unsigned msk = __ballot_sync(0xffffffffu, ok);
        int p2 = count + __popc(msk & ((1u << lane) - 1u));
        if (ok && p2 < KN) out[p2] = m;
        count += __popc(msk);
        if (count > KN) count = KN;
    }
    for (int p2 = count + lane; p2 < KN; p2 += 32) out[p2] = BQ_N;
}

// ---------------- kernel-point correlation: wf (S, R1*C) -------------------
__global__ void kp_wf_kernel(const float* __restrict__ pos,
                             const int* __restrict__ idx,
                             const float* __restrict__ qp,
                             const float* __restrict__ feat0,
                             float* __restrict__ wf) {
    int s = blockIdx.x;
    int b = s >> 12, n = s & (BQ_N - 1);
    int c = threadIdx.x;
    __shared__ float wsh[R1][KN];
    __shared__ int nidx[KN];
    if (c < KN) {
        int m = idx[(size_t)s * KN + c];
        nidx[c] = m;
        float wr[R1];
#pragma unroll
        for (int r = 0; r < R1; r++) wr[r] = 0.f;
        if (m < BQ_N) {
            const float* p = pos + (size_t)b * 3 * BQ_N;
            float rx = p[m] - p[n];
            float ry = p[BQ_N + m] - p[BQ_N + n];
            float rz = p[2 * BQ_N + m] - p[2 * BQ_N + n];
#pragma unroll
            for (int r = 0; r < R1; r++) {
                float dx = rx - qp[r];
                float dy = ry - qp[R1 + r];
                float dz = rz - qp[2 * R1 + r];
                float d = sqrtf(dx * dx + dy * dy + dz * dz);
                wr[r] = fmaxf(0.f, 1.f - d / 0.1f);
            }
        }
#pragma unroll
        for (int r = 0; r < R1; r++) wsh[r][c] = wr[r];
    }
    __syncthreads();
    float acc[R1] = {0.f, 0.f, 0.f, 0.f, 0.f};
#pragma unroll 4
    for (int k = 0; k < KN; k++) {
        int m = nidx[k];
        float f = (m < BQ_N) ? feat0[(size_t)(b * BQ_N + m) * CC + c] : 0.f;
#pragma unroll
        for (int r = 0; r < R1; r++) acc[r] += wsh[r][k] * f;
    }
#pragma unroll
    for (int r = 0; r < R1; r++)
        wf[(size_t)s * (R1 * CC) + r * CC + c] = acc[r];
}

// ---- prep: split all weights hi/lo, bias2d, the 12 query_pos outputs ------
__device__ __forceinline__ void split_store(float* dst, int i, float v) {
    uint32_t hi = __float_as_uint(v) & 0xFFFFE000u;
    dst[2 * i]     = __uint_as_float(hi);
    dst[2 * i + 1] = v - __uint_as_float(hi);
}

__global__ void prep_kernel(const float* __restrict__ w_begin,
                            const float* __restrict__ kpw,
                            const float* __restrict__ w_end,
                            const float* __restrict__ w1,
                            const float* __restrict__ w2,
                            const float* __restrict__ qp,
                            float* __restrict__ wbs, float* __restrict__ kpTs,
                            float* __restrict__ wes, float* __restrict__ w1as,
                            float* __restrict__ w1cds, float* __restrict__ m2s,
                            float* __restrict__ bias2d,
                            float* __restrict__ out12) {
    int id = blockIdx.x * blockDim.x + threadIdx.x;
    int t = id;
    if (t < 16384) {                              // w_begin (o=128, k=128)
        int o = t >> 7, k = t & 127;
        split_store(wbs + (size_t)o * 256, k, w_begin[o * 128 + k]);
        return;
    }
    t -= 16384;
    if (t < 81920) {                              // kpT (c=128, k=640)
        int c = t / 640, k = t % 640;
        split_store(kpTs + (size_t)c * 1280, k, kpw[(size_t)k * 128 + c]);
        return;
    }
    t -= 81920;
    if (t < 16384) {                              // w_end (128,128)
        int o = t >> 7, k = t & 127;
        split_store(wes + (size_t)o * 256, k, w_end[o * 128 + k]);
        return;
    }
    t -= 16384;
    if (t < 32768) {                              // w1a (256,128): cols 0..127
        int o = t >> 7, k = t & 127;
        split_store(w1as + (size_t)o * 256, k, w1[(size_t)o * 387 + k]);
        return;
    }
    t -= 32768;
    if (t < 65536) {                              // w1cd (256,256): cols 131..386
        int o = t >> 8, k = t & 255;
        split_store(w1cds + (size_t)o * 512, k, w1[(size_t)o * 387 + 131 + k]);
        return;
    }
    t -= 65536;
    if (t < 32768) {                              // w_mlp2 (128,256)
        int o = t >> 8, k = t & 255;
        split_store(m2s + (size_t)o * 512, k, w2[(size_t)o * 256 + k]);
        return;
    }
    t -= 32768;
    if (t < 1024) {                               // bias2d[r][n] = sum_a W1[n][128+a]*qp[a][r+1]
        int r = t >> 8, n = t & 255;
        float s = 0.f;
#pragma unroll
        for (int a = 0; a < 3; a++)
            s += w1[(size_t)n * 387 + 128 + a] * qp[a * R1 + r + 1];
        bias2d[r * 256 + n] = s;
        return;
    }
    t -= 1024;
    if (t < 12) {                                 // query_pos output (3,4)
        int a = t >> 2, r = (t & 3) + 1;
        out12[t] = qp[a * R1 + r];
    }
}

// ---------------- launch ----------------------------------------------------
extern "C" void kernel_launch(void* const* d_in, const int* in_sizes, int n_in,
                              void* d_out, int out_size) {
    (void)in_sizes; (void)n_in; (void)out_size;
    const float* pos       = (const float*)d_in[0];
    const float* feat      = (const float*)d_in[1];
    const float* qp        = (const float*)d_in[2];
    const float* w_begin   = (const float*)d_in[3];
    const float* b_begin   = (const float*)d_in[4];
    const float* kp_weight = (const float*)d_in[5];
    const float* kp_bias   = (const float*)d_in[6];
    const float* w_end     = (const float*)d_in[7];
    const float* b_end     = (const float*)d_in[8];
    const float* w_mlp1    = (const float*)d_in[9];
    const float* b_mlp1    = (const float*)d_in[10];
    const float* w_mlp2    = (const float*)d_in[11];
    const float* b_mlp2    = (const float*)d_in[12];
    float* out = (float*)d_out;

    float *featT, *feat0, *wf, *qf, *qf2, *Y, *h;
    float *wbs, *kpTs, *wes, *w1as, *w1cds, *m2s, *bias2d;
    int* idx;
    cudaGetSymbolAddress((void**)&featT, g_featT);
    cudaGetSymbolAddress((void**)&feat0, g_feat0);
    cudaGetSymbolAddress((void**)&idx,   g_idx);
    cudaGetSymbolAddress((void**)&wf,    g_wf);
    cudaGetSymbolAddress((void**)&qf,    g_qf);
    cudaGetSymbolAddress((void**)&qf2,   g_qf2);
    cudaGetSymbolAddress((void**)&Y,     g_Y);
    cudaGetSymbolAddress((void**)&h,     g_h);
    cudaGetSymbolAddress((void**)&wbs,   g_wbs);
    cudaGetSymbolAddress((void**)&kpTs,  g_kpTs);
    cudaGetSymbolAddress((void**)&wes,   g_wes);
    cudaGetSymbolAddress((void**)&w1as,  g_w1as);
    cudaGetSymbolAddress((void**)&w1cds, g_w1cds);
    cudaGetSymbolAddress((void**)&m2s,   g_m2s);
    cudaGetSymbolAddress((void**)&bias2d, g_bias2d);

    const int SMEM_DYN = 2 * 13824 * 4;   // 110592 B
    cudaFuncSetAttribute(mma_gemm<0, false, false, false, false, false>,
                         cudaFuncAttributeMaxDynamicSharedMemorySize, SMEM_DYN);
    cudaFuncSetAttribute(mma_gemm<0, true, false, false, false, false>,
                         cudaFuncAttributeMaxDynamicSharedMemorySize, SMEM_DYN);
    cudaFuncSetAttribute(mma_gemm<0, true, true, false, false, false>,
                         cudaFuncAttributeMaxDynamicSharedMemorySize, SMEM_DYN);
    cudaFuncSetAttribute(mma_gemm<2, false, false, false, false, false>,
                         cudaFuncAttributeMaxDynamicSharedMemorySize, SMEM_DYN);
    cudaFuncSetAttribute(mma_gemm<1, true, true, true, true, false>,
                         cudaFuncAttributeMaxDynamicSharedMemorySize, SMEM_DYN);
    cudaFuncSetAttribute(mma_gemm<0, true, false, false, false, true>,
                         cudaFuncAttributeMaxDynamicSharedMemorySize, SMEM_DYN);

    // Stage 0: transpose + ball query + prep (splits, bias2d, 12 outputs)
    transpose_kernel<<<dim3(128, 4, 4), dim3(32, 8)>>>(feat, featT);
    ballquery_kernel<<<dim3(512, 4), 256>>>(pos, idx);
    {
        int total = 16384 + 81920 + 16384 + 32768 + 65536 + 32768 + 1024 + 12;
        prep_kernel<<<(total + 255) / 256, 256>>>(
            w_begin, kp_weight, w_end, w_mlp1, w_mlp2, qp,
            wbs, kpTs, wes, w1as, w1cds, m2s, bias2d, out);
    }

    // feat0 = featT @ w_begin^T + b_begin
    mma_gemm<0, false, false, false, false, false><<<dim3(1, 128), 256, SMEM_DYN>>>(
        S_TOT, 128, 128, featT, nullptr, wbs, b_begin, nullptr, feat0);

    // kernel-point correlation -> wf (S, 640)
    kp_wf_kernel<<<S_TOT, 128>>>(pos, idx, qp, feat0, wf);

    // qf = relu(wf @ kpT^T + kp_bias)
    mma_gemm<0, true, false, false, false, false><<<dim3(1, 128), 256, SMEM_DYN>>>(
        S_TOT, 128, 640, wf, nullptr, kpTs, kp_bias, nullptr, qf);

    // qf2 = relu(qf @ w_end^T + b_end + featT)
    mma_gemm<0, true, true, false, false, false><<<dim3(1, 128), 256, SMEM_DYN>>>(
        S_TOT, 128, 128, qf, nullptr, wes, b_end, featT, qf2);

    // Y = [qf2 | featT] @ w1cd^T + b_mlp1      (r-independent half of MLP1)
    mma_gemm<2, false, false, false, false, false><<<dim3(2, 128), 256, SMEM_DYN>>>(
        S_TOT, 256, 256, qf2, featT, w1cds, b_mlp1, nullptr, Y);

    // h = relu(wf_r @ w1a^T + bias2d[r] + Y[s])
    mma_gemm<1, true, true, true, true, false><<<dim3(2, 512), 256, SMEM_DYN>>>(
        S2_TOT, 256, 128, wf, nullptr, w1as, bias2d, Y, h);

    // queries = relu(h @ w_mlp2^T + b_mlp2), scattered to (B, TD, N, R)
    mma_gemm<0, true, false, false, false, true><<<dim3(1, 512), 256, SMEM_DYN>>>(
        S2_TOT, 128, 256, h, nullptr, m2s, b_mlp2, nullptr, out + 12);
}

// round 6
// speedup vs baseline: 2.4951x; 1.2685x over previous
#include <cuda_runtime.h>
#include <cuda_bf16.h>
#include <cstdint>

// Problem constants (fixed shapes)
#define BQ_N 4096
#define NB 4
#define CC 128
#define KN 32
#define R1 5
#define S_TOT (NB * BQ_N)        // 16384 samples
#define S2_TOT (S_TOT * 4)       // 65536 (sample, r) columns
#define CONV_R2 0.04f            // (0.2)^2

// ---------------- scratch (device globals; no allocation allowed) ----------
// Packed activation format: element k lives as bf16 in u32 pair:
//   u32[m*K + (k&~1)]   = bf16x2(hi(k_even), hi(k_odd))
//   u32[m*K + (k&~1)+1] = bf16x2(lo(k_even), lo(k_odd))
__device__ uint32_t g_featT[S_TOT * CC];
__device__ uint32_t g_feat0[S_TOT * CC];
__device__ int      g_idx[S_TOT * KN];
__device__ uint32_t g_wf[(size_t)S_TOT * R1 * CC];
__device__ uint32_t g_qf[S_TOT * CC];
__device__ uint32_t g_qf2[S_TOT * CC];
__device__ float    g_Y[(size_t)S_TOT * 256];       // fp32 (resid only)
__device__ uint32_t g_h[(size_t)S2_TOT * 256];
// packed weights (N, K) u32
__device__ uint32_t g_wbs[128 * 128];
__device__ uint32_t g_kpTs[128 * 640];
__device__ uint32_t g_wes[128 * 128];
__device__ uint32_t g_w1as[256 * 128];
__device__ uint32_t g_w1cds[256 * 256];
__device__ uint32_t g_m2s[128 * 256];
__device__ float    g_bias2d[4 * 256];

__device__ __forceinline__ uint32_t smem_u32(const void* p) {
    uint32_t a;
    asm("{ .reg .u64 t; cvta.to.shared.u64 t, %1; cvt.u32.u64 %0, t; }"
        : "=r"(a) : "l"(p));
    return a;
}

__device__ __forceinline__ uint32_t bf2_pack(float v0, float v1) {
    __nv_bfloat162 h = __floats2bfloat162_rn(v0, v1);
    return *reinterpret_cast<uint32_t*>(&h);
}
__device__ __forceinline__ float2 bf2_unpack(uint32_t u) {
    __nv_bfloat162 h = *reinterpret_cast<__nv_bfloat162*>(&u);
    return make_float2(__bfloat162float(h.x), __bfloat162float(h.y));
}
__device__ __forceinline__ uint2 pack_hilo(float v0, float v1) {
    uint32_t hi = bf2_pack(v0, v1);
    float2 hf = bf2_unpack(hi);
    uint32_t lo = bf2_pack(v0 - hf.x, v1 - hf.y);
    return make_uint2(hi, lo);
}

#define MMA_BF16(d, a0, a1, a2, a3, b0, b1) \
    asm volatile( \
        "mma.sync.aligned.m16n8k16.row.col.f32.bf16.bf16.f32 " \
        "{%0,%1,%2,%3}, {%4,%5,%6,%7}, {%8,%9}, {%0,%1,%2,%3};" \
        : "+f"((d)[0]), "+f"((d)[1]), "+f"((d)[2]), "+f"((d)[3]) \
        : "r"(a0), "r"(a1), "r"(a2), "r"(a3), "r"(b0), "r"(b1))

// ---------------- bf16x3 mma.sync GEMM, packed hi/lo operands ---------------
// C[M, 128-tile of Ng] = epi(A @ B^T + bias); ~fp32 accuracy (hi*hi+hi*lo+lo*hi).
// A/Bs: packed u32 arrays, K u32 per row.
// AMODE 0: row-major (M,K). 1: m -> wf[s=m>>2] slice (m&3)+1 (K=128).
//          2: kt<4 from A (row=128u32), kt>=4 from A2.
// RESID 0: none; 1: packed bf16 hi/lo; 2: fp32.
// Smem: pair-XOR swizzle s=q^((row&3)<<2), stride 32 u32; 2 stages x 32KB.
template <int AMODE, bool RELU, int RESID, bool RBCAST, bool BIAS2D, bool PERM, bool PACKOUT>
__global__ void __launch_bounds__(256, 2)
mma_gemm(int M, int Ng, int K,
         const uint32_t* __restrict__ A, const uint32_t* __restrict__ A2,
         const uint32_t* __restrict__ Bs,
         const float* __restrict__ bias, const void* __restrict__ resid,
         float* __restrict__ C) {
    extern __shared__ uint32_t smu[];
    const int SSTRIDE = 8192;
    int tid = threadIdx.x;
    int lane = tid & 31, wid = tid >> 5;
    int wm = wid & 3, wn = wid >> 2;
    int m0 = blockIdx.y << 7, n0 = blockIdx.x << 7;
    int nK = K >> 5;

    float acc[2][8][4];
#pragma unroll
    for (int mi = 0; mi < 2; mi++)
#pragma unroll
        for (int ni = 0; ni < 8; ni++)
#pragma unroll
            for (int u = 0; u < 4; u++) acc[mi][ni][u] = 0.f;

    auto load_tile = [&](int kt) {
        uint32_t* dst = smu + (kt & 1) * SSTRIDE;
#pragma unroll
        for (int i = 0; i < 4; i++) {              // A tile 128 rows x 32 u32
            int c = tid + (i << 8);
            int row = c >> 3, j = c & 7;
            const uint32_t* g;
            if (AMODE == 0) {
                g = A + (size_t)(m0 + row) * K + (kt << 5) + (j << 2);
            } else if (AMODE == 1) {
                int m = m0 + row;
                g = A + (size_t)(m >> 2) * 640 + (((m & 3) + 1) << 7) + (kt << 5) + (j << 2);
            } else {
                const uint32_t* base = (kt < 4) ? A : A2;
                g = base + ((size_t)(m0 + row) << 7) + ((kt & 3) << 5) + (j << 2);
            }
            int ch = j ^ ((row & 3) << 1);
            uint32_t sa = smem_u32(dst + (row << 5) + (ch << 2));
            asm volatile("cp.async.cg.shared.global [%0], [%1], 16;"
                         :: "r"(sa), "l"(g) : "memory");
        }
#pragma unroll
        for (int i = 0; i < 4; i++) {              // B tile 128 rows x 32 u32
            int c = tid + (i << 8);
            int row = c >> 3, j = c & 7;
            const uint32_t* g = Bs + (size_t)(n0 + row) * K + (kt << 5) + (j << 2);
            int ch = j ^ ((row & 3) << 1);
            uint32_t sa = smem_u32(dst + 4096 + (row << 5) + (ch << 2));
            asm volatile("cp.async.cg.shared.global [%0], [%1], 16;"
                         :: "r"(sa), "l"(g) : "memory");
        }
        asm volatile("cp.async.commit_group;" ::: "memory");
    };

    load_tile(0);
    int g = lane >> 2, kc = lane & 3;
    int swz = (g & 3) << 2;
    int arow = wm * 32 + g;
    int brow = wn * 64 + g;

    for (int kt = 0; kt < nK; kt++) {
        if (kt + 1 < nK) {
            load_tile(kt + 1);
            asm volatile("cp.async.wait_group 1;" ::: "memory");
        } else {
            asm volatile("cp.async.wait_group 0;" ::: "memory");
        }
        __syncthreads();
        const uint32_t* Asb = smu + (kt & 1) * SSTRIDE;
        const uint32_t* Bsb = Asb + 4096;
#pragma unroll
        for (int ks = 0; ks < 2; ks++) {
            int o1 = 2 * ((ks * 8 + kc) ^ swz);
            int o2 = 2 * ((ks * 8 + kc + 4) ^ swz);
            uint2 Af[2][4];
#pragma unroll
            for (int mi = 0; mi < 2; mi++) {
                const uint32_t* p = Asb + ((arow + mi * 16) << 5);
                Af[mi][0] = *(const uint2*)(p + o1);
                Af[mi][1] = *(const uint2*)(p + 256 + o1);    // +8 rows
                Af[mi][2] = *(const uint2*)(p + o2);
                Af[mi][3] = *(const uint2*)(p + 256 + o2);
            }
#pragma unroll
            for (int ni = 0; ni < 8; ni++) {
                const uint32_t* bp = Bsb + ((brow + ni * 8) << 5);
                uint2 B0 = *(const uint2*)(bp + o1);
                uint2 B1 = *(const uint2*)(bp + o2);
#pragma unroll
                for (int mi = 0; mi < 2; mi++) {
                    MMA_BF16(acc[mi][ni], Af[mi][0].x, Af[mi][1].x, Af[mi][2].x, Af[mi][3].x, B0.x, B1.x);
                    MMA_BF16(acc[mi][ni], Af[mi][0].x, Af[mi][1].x, Af[mi][2].x, Af[mi][3].x, B0.y, B1.y);
                    MMA_BF16(acc[mi][ni], Af[mi][0].y, Af[mi][1].y, Af[mi][2].y, Af[mi][3].y, B0.x, B1.x);
                }
            }
        }
        __syncthreads();
    }

    // Epilogue. c0:(g,2t) c1:(g,2t+1) c2:(g+8,2t) c3:(g+8,2t+1)
    int mrow = m0 + wm * 32 + g;
    int rsel = mrow & 3;
    int nc0 = n0 + wn * 64 + 2 * kc;
    const uint32_t* Rp = (const uint32_t*)resid;
    const float* Rf = (const float*)resid;
#pragma unroll
    for (int ni = 0; ni < 8; ni++) {
        int n = nc0 + ni * 8;
        int boff = BIAS2D ? rsel * Ng : 0;
        float bv0 = bias[boff + n], bv1 = bias[boff + n + 1];
#pragma unroll
        for (int mi = 0; mi < 2; mi++) {
#pragma unroll
            for (int h2 = 0; h2 < 2; h2++) {
                int m = mrow + mi * 16 + h2 * 8;
                float x0 = acc[mi][ni][2 * h2]     + bv0;
                float x1 = acc[mi][ni][2 * h2 + 1] + bv1;
                if (RESID == 1) {
                    uint2 rv = *(const uint2*)(Rp + (size_t)m * Ng + n);
                    float2 rh = bf2_unpack(rv.x), rl = bf2_unpack(rv.y);
                    x0 += rh.x + rl.x;
                    x1 += rh.y + rl.y;
                } else if (RESID == 2) {
                    size_t rr = RBCAST ? ((size_t)(m >> 2) * Ng + n)
                                       : ((size_t)m * Ng + n);
                    x0 += Rf[rr];
                    x1 += Rf[rr + 1];
                }
                if (RELU) { x0 = fmaxf(x0, 0.f); x1 = fmaxf(x1, 0.f); }
                if (PERM) {
                    // m = (b*4096+pt)*4+r ; out idx = ((b*128+d)*4096+pt)*4+r
                    int bb = m >> 14;
                    size_t low = (size_t)(m & 16383);
                    C[(((size_t)(bb * 128 + n)) << 14) + low] = x0;
                    C[(((size_t)(bb * 128 + n + 1)) << 14) + low] = x1;
                } else if (PACKOUT) {
                    uint2 pw = pack_hilo(x0, x1);
                    *(uint2*)((uint32_t*)C + (size_t)m * Ng + n) = pw;
                } else {
                    *(float2*)(C + (size_t)m * Ng + n) = make_float2(x0, x1);
                }
            }
        }
    }
}

// ------------- transpose feat (B,C,N) -> packed featT (B,N,C) --------------
__global__ void transpose_kernel(const float* __restrict__ feat,
                                 uint32_t* __restrict__ featT) {
    __shared__ float tile[32][33];
    int b = blockIdx.z;
    int n0 = blockIdx.x * 32, c0 = blockIdx.y * 32;
    int tx = threadIdx.x, ty = threadIdx.y;
#pragma unroll
    for (int i = ty; i < 32; i += 8)
        tile[i][tx] = feat[((size_t)(b * CC + c0 + i)) * BQ_N + n0 + tx];
    __syncthreads();
#pragma unroll
    for (int i = ty; i < 32; i += 8) {
        float v = tile[tx][i];
        float vp = __shfl_xor_sync(0xffffffffu, v, 1);
        if (!(tx & 1)) {
            uint2 pw = pack_hilo(v, vp);
            *(uint2*)(featT + (((size_t)(b * BQ_N + n0 + i)) << 7) + c0 + tx) = pw;
        }
    }
}

// ---------------- ball query: first 32 in-radius neighbors by index --------
__global__ void ballquery_kernel(const float* __restrict__ pos,
                                 int* __restrict__ idx) {
    __shared__ float sx[BQ_N], sy[BQ_N], sz[BQ_N];
    int b = blockIdx.y;
    const float* p = pos + (size_t)b * 3 * BQ_N;
    for (int i = threadIdx.x; i < BQ_N; i += blockDim.x) {
        sx[i] = p[i];
        sy[i] = p[BQ_N + i];
        sz[i] = p[2 * BQ_N + i];
    }
    __syncthreads();
    int warp = threadIdx.x >> 5, lane = threadIdx.x & 31;
    int n = blockIdx.x * (blockDim.x >> 5) + warp;
    float xn = sx[n], yn = sy[n], zn = sz[n];
    float nn = xn * xn + yn * yn + zn * zn;
    int* out = idx + (size_t)(b * BQ_N + n) * KN;
    int count = 0;
    for (int m0 = 0; m0 < BQ_N && count < KN; m0 += 32) {
        int m = m0 + lane;
        float xm = sx[m], ym = sy[m], zm = sz[m];
        float nm = xm * xm + ym * ym + zm * zm;
        float dt = xn * xm + yn * ym + zn * zm;
        float sqd = (nn + nm) - 2.0f * dt;
        bool ok = (sqd <= CONV_R2);
        unsigned msk = __ballot_sync(0xffffffffu, ok);
        int p2 = count + __popc(msk & ((1u << lane) - 1u));
        if (ok && p2 < KN) out[p2] = m;
        count += __popc(msk);
        if (count > KN) count = KN;
    }
    for (int p2 = count + lane; p2 < KN; p2 += 32) out[p2] = BQ_N;
}

// -------- kernel-point correlation: packed feat0 -> packed wf --------------
__global__ void kp_wf_kernel(const float* __restrict__ pos,
                             const int* __restrict__ idx,
                             const float* __restrict__ qp,
                             const uint32_t* __restrict__ feat0,
                             uint32_t* __restrict__ wf) {
    int s = blockIdx.x;
    int b = s >> 12, n = s & (BQ_N - 1);
    int c = threadIdx.x;
    __shared__ float wsh[R1][KN];
    __shared__ int nidx[KN];
    if (c < KN) {
        int m = idx[(size_t)s * KN + c];
        nidx[c] = m;
        float wr[R1];
#pragma unroll
        for (int r = 0; r < R1; r++) wr[r] = 0.f;
        if (m < BQ_N) {
            const float* p = pos + (size_t)b * 3 * BQ_N;
            float rx = p[m] - p[n];
            float ry = p[BQ_N + m] - p[BQ_N + n];
            float rz = p[2 * BQ_N + m] - p[2 * BQ_N + n];
#pragma unroll
            for (int r = 0; r < R1; r++) {
                float dx = rx - qp[r];
                float dy = ry - qp[R1 + r];
                float dz = rz - qp[2 * R1 + r];
                float d = sqrtf(dx * dx + dy * dy + dz * dz);
                wr[r] = fmaxf(0.f, 1.f - d / 0.1f);
            }
        }
#pragma unroll
        for (int r = 0; r < R1; r++) wsh[r][c] = wr[r];
    }
    __syncthreads();
    float acc[R1] = {0.f, 0.f, 0.f, 0.f, 0.f};
    bool odd = (c & 1);
    int ce = c & ~1;
#pragma unroll 4
    for (int k = 0; k < KN; k++) {
        int m = nidx[k];
        float f = 0.f;
        if (m < BQ_N) {
            uint2 w = *(const uint2*)(feat0 + (((size_t)(b * BQ_N + m)) << 7) + ce);
            float2 hh = bf2_unpack(w.x), ll = bf2_unpack(w.y);
            f = odd ? (hh.y + ll.y) : (hh.x + ll.x);
        }
#pragma unroll
        for (int r = 0; r < R1; r++) acc[r] += wsh[r][k] * f;
    }
#pragma unroll
    for (int r = 0; r < R1; r++) {
        float v = acc[r];
        float vp = __shfl_xor_sync(0xffffffffu, v, 1);
        if (!odd) {
            uint2 pw = pack_hilo(v, vp);
            *(uint2*)(wf + (size_t)s * 640 + r * 128 + c) = pw;
        }
    }
}

// ---- prep: pack all weights hi/lo, bias2d, the 12 query_pos outputs -------
__global__ void prep_kernel(const float* __restrict__ w_begin,
                            const float* __restrict__ kpw,
                            const float* __restrict__ w_end,
                            const float* __restrict__ w1,
                            const float* __restrict__ w2,
                            const float* __restrict__ qp,
                            uint32_t* __restrict__ wbs, uint32_t* __restrict__ kpTs,
                            uint32_t* __restrict__ wes, uint32_t* __restrict__ w1as,
                            uint32_t* __restrict__ w1cds, uint32_t* __restrict__ m2s,
                            float* __restrict__ bias2d,
                            float* __restrict__ out12) {
    int t = blockIdx.x * blockDim.x + threadIdx.x;
    if (t < 8192) {                              // w_begin (128,128): 64 pairs/row
        int o = t >> 6, p = t & 63;
        *(uint2*)(wbs + o * 128 + 2 * p) =
            pack_hilo(w_begin[o * 128 + 2 * p], w_begin[o * 128 + 2 * p + 1]);
        return;
    }
    t -= 8192;
    if (t < 40960) {                             // kpT (128,640): 320 pairs/row
        int c = t / 320, p = t % 320;
        *(uint2*)(kpTs + (size_t)c * 640 + 2 * p) =
            pack_hilo(kpw[(size_t)(2 * p) * 128 + c], kpw[(size_t)(2 * p + 1) * 128 + c]);
        return;
    }
    t -= 40960;
    if (t < 8192) {                              // w_end (128,128)
        int o = t >> 6, p = t & 63;
        *(uint2*)(wes + o * 128 + 2 * p) =
            pack_hilo(w_end[o * 128 + 2 * p], w_end[o * 128 + 2 * p + 1]);
        return;
    }
    t -= 8192;
    if (t < 16384) {                             // w1a (256,128): cols 0..127
        int o = t >> 6, p = t & 63;
        *(uint2*)(w1as + o * 128 + 2 * p) =
            pack_hilo(w1[(size_t)o * 387 + 2 * p], w1[(size_t)o * 387 + 2 * p + 1]);
        return;
    }
    t -= 16384;
    if (t < 32768) {                             // w1cd (256,256): cols 131..386
        int o = t >> 7, p = t & 127;
        *(uint2*)(w1cds + (size_t)o * 256 + 2 * p) =
            pack_hilo(w1[(size_t)o * 387 + 131 + 2 * p], w1[(size_t)o * 387 + 132 + 2 * p]);
        return;
    }
    t -= 32768;
    if (t < 16384) {                             // w_mlp2 (128,256)
        int o = t >> 7, p = t & 127;
        *(uint2*)(m2s + (size_t)o * 256 + 2 * p) =
            pack_hilo(w2[(size_t)o * 256 + 2 * p], w2[(size_t)o * 256 + 2 * p + 1]);
        return;
    }
    t -= 16384;
    if (t < 1024) {                              // bias2d[r][n] = sum_a W1[n][128+a]*qp[a][r+1]
        int r = t >> 8, n = t & 255;
        float s = 0.f;
#pragma unroll
        for (int a = 0; a < 3; a++)
            s += w1[(size_t)n * 387 + 128 + a] * qp[a * R1 + r + 1];
        bias2d[r * 256 + n] = s;
        return;
    }
    t -= 1024;
    if (t < 12) {                                // query_pos output (3,4)
        int a = t >> 2, r = (t & 3) + 1;
        out12[t] = qp[a * R1 + r];
    }
}

// ---------------- launch ----------------------------------------------------
extern "C" void kernel_launch(void* const* d_in, const int* in_sizes, int n_in,
                              void* d_out, int out_size) {
    (void)in_sizes; (void)n_in; (void)out_size;
    const float* pos       = (const float*)d_in[0];
    const float* feat      = (const float*)d_in[1];
    const float* qp        = (const float*)d_in[2];
    const float* w_begin   = (const float*)d_in[3];
    const float* b_begin   = (const float*)d_in[4];
    const float* kp_weight = (const float*)d_in[5];
    const float* kp_bias   = (const float*)d_in[6];
    const float* w_end     = (const float*)d_in[7];
    const float* b_end     = (const float*)d_in[8];
    const float* w_mlp1    = (const float*)d_in[9];
    const float* b_mlp1    = (const float*)d_in[10];
    const float* w_mlp2    = (const float*)d_in[11];
    const float* b_mlp2    = (const float*)d_in[12];
    float* out = (float*)d_out;

    uint32_t *featT, *feat0, *wf, *qf, *qf2, *h;
    uint32_t *wbs, *kpTs, *wes, *w1as, *w1cds, *m2s;
    float *Y, *bias2d;
    int* idx;
    cudaGetSymbolAddress((void**)&featT, g_featT);
    cudaGetSymbolAddress((void**)&feat0, g_feat0);
    cudaGetSymbolAddress((void**)&idx,   g_idx);
    cudaGetSymbolAddress((void**)&wf,    g_wf);
    cudaGetSymbolAddress((void**)&qf,    g_qf);
    cudaGetSymbolAddress((void**)&qf2,   g_qf2);
    cudaGetSymbolAddress((void**)&Y,     g_Y);
    cudaGetSymbolAddress((void**)&h,     g_h);
    cudaGetSymbolAddress((void**)&wbs,   g_wbs);
    cudaGetSymbolAddress((void**)&kpTs,  g_kpTs);
    cudaGetSymbolAddress((void**)&wes,   g_wes);
    cudaGetSymbolAddress((void**)&w1as,  g_w1as);
    cudaGetSymbolAddress((void**)&w1cds, g_w1cds);
    cudaGetSymbolAddress((void**)&m2s,   g_m2s);
    cudaGetSymbolAddress((void**)&bias2d, g_bias2d);

    const int SMEM_DYN = 2 * 8192 * 4;   // 65536 B
#define SETSM(...) cudaFuncSetAttribute(mma_gemm<__VA_ARGS__>, \
        cudaFuncAttributeMaxDynamicSharedMemorySize, SMEM_DYN)
    SETSM(0, false, 0, false, false, false, true);
    SETSM(0, true,  0, false, false, false, true);
    SETSM(0, true,  1, false, false, false, true);
    SETSM(2, false, 0, false, false, false, false);
    SETSM(1, true,  2, true,  true,  false, true);
    SETSM(0, true,  0, false, false, true,  false);
#undef SETSM

    // Stage 0: transpose(+pack) + ball query + prep (packs, bias2d, 12 outputs)
    transpose_kernel<<<dim3(128, 4, 4), dim3(32, 8)>>>(feat, featT);
    ballquery_kernel<<<dim3(512, 4), 256>>>(pos, idx);
    {
        int total = 8192 + 40960 + 8192 + 16384 + 32768 + 16384 + 1024 + 12;
        prep_kernel<<<(total + 255) / 256, 256>>>(
            w_begin, kp_weight, w_end, w_mlp1, w_mlp2, qp,
            wbs, kpTs, wes, w1as, w1cds, m2s, bias2d, out);
    }

    // feat0 = featT @ w_begin^T + b_begin          (packed out)
    mma_gemm<0, false, 0, false, false, false, true><<<dim3(1, 128), 256, SMEM_DYN>>>(
        S_TOT, 128, 128, featT, nullptr, wbs, b_begin, nullptr, (float*)feat0);

    // kernel-point correlation -> wf (S, 640)      (packed out)
    kp_wf_kernel<<<S_TOT, 128>>>(pos, idx, qp, feat0, wf);

    // qf = relu(wf @ kpT^T + kp_bias)              (packed out)
    mma_gemm<0, true, 0, false, false, false, true><<<dim3(1, 128), 256, SMEM_DYN>>>(
        S_TOT, 128, 640, wf, nullptr, kpTs, kp_bias, nullptr, (float*)qf);

    // qf2 = relu(qf @ w_end^T + b_end + featT)     (packed resid, packed out)
    mma_gemm<0, true, 1, false, false, false, true><<<dim3(1, 128), 256, SMEM_DYN>>>(
        S_TOT, 128, 128, qf, nullptr, wes, b_end, featT, (float*)qf2);

    // Y = [qf2 | featT] @ w1cd^T + b_mlp1          (fp32 out; resid for h)
    mma_gemm<2, false, 0, false, false, false, false><<<dim3(2, 128), 256, SMEM_DYN>>>(
        S_TOT, 256, 256, qf2, featT, w1cds, b_mlp1, nullptr, Y);

    // h = relu(wf_r @ w1a^T + bias2d[r] + Y[s])    (packed out)
    mma_gemm<1, true, 2, true, true, false, true><<<dim3(2, 512), 256, SMEM_DYN>>>(
        S2_TOT, 256, 128, wf, nullptr, w1as, bias2d, Y, (float*)h);

    // queries = relu(h @ w_mlp2^T + b_mlp2), scattered to (B, TD, N, R)
    mma_gemm<0, true, 0, false, false, true, false><<<dim3(1, 512), 256, SMEM_DYN>>>(
        S2_TOT, 128, 256, h, nullptr, m2s, b_mlp2, nullptr, out + 12);
}

// round 8
// speedup vs baseline: 2.5241x; 1.0116x over previous
#include <cuda_runtime.h>
#include <cuda_bf16.h>
#include <cstdint>

// Problem constants (fixed shapes)
#define BQ_N 4096
#define NB 4
#define CC 128
#define KN 32
#define R1 5
#define S_TOT (NB * BQ_N)        // 16384 samples
#define S2_TOT (S_TOT * 4)       // 65536 (sample, r) columns
#define CONV_R2 0.04f            // (0.2)^2

// ---------------- scratch (device globals; no allocation allowed) ----------
// Packed activation format: element k lives as bf16 in u32 pair:
//   u32[m*K + (k&~1)]   = bf16x2(hi(k_even), hi(k_odd))
//   u32[m*K + (k&~1)+1] = bf16x2(lo(k_even), lo(k_odd))
__device__ uint32_t g_featT[S_TOT * CC];
__device__ uint32_t g_feat0[S_TOT * CC];
__device__ int      g_idx[S_TOT * KN];
__device__ uint32_t g_wf[(size_t)S_TOT * R1 * CC];
__device__ uint32_t g_qf[S_TOT * CC];
__device__ uint32_t g_qf2[S_TOT * CC];
__device__ float    g_Y[(size_t)S_TOT * 256];       // fp32 (resid only)
__device__ uint32_t g_h[(size_t)S2_TOT * 256];
// packed weights (N, K) u32
__device__ uint32_t g_wbs[128 * 128];
__device__ uint32_t g_kpTs[128 * 640];
__device__ uint32_t g_wes[128 * 128];
__device__ uint32_t g_w1as[256 * 128];
__device__ uint32_t g_w1cds[256 * 256];
__device__ uint32_t g_m2s[128 * 256];
__device__ float    g_bias2d[4 * 256];

__device__ __forceinline__ uint32_t smem_u32(const void* p) {
    uint32_t a;
    asm("{ .reg .u64 t; cvta.to.shared.u64 t, %1; cvt.u32.u64 %0, t; }"
        : "=r"(a) : "l"(p));
    return a;
}

__device__ __forceinline__ uint32_t bf2_pack(float v0, float v1) {
    __nv_bfloat162 h = __floats2bfloat162_rn(v0, v1);
    return *reinterpret_cast<uint32_t*>(&h);
}
__device__ __forceinline__ float2 bf2_unpack(uint32_t u) {
    __nv_bfloat162 h = *reinterpret_cast<__nv_bfloat162*>(&u);
    return make_float2(__bfloat162float(h.x), __bfloat162float(h.y));
}
__device__ __forceinline__ uint2 pack_hilo(float v0, float v1) {
    uint32_t hi = bf2_pack(v0, v1);
    float2 hf = bf2_unpack(hi);
    uint32_t lo = bf2_pack(v0 - hf.x, v1 - hf.y);
    return make_uint2(hi, lo);
}

#define MMA_BF16(d, a0, a1, a2, a3, b0, b1) \
    asm volatile( \
        "mma.sync.aligned.m16n8k16.row.col.f32.bf16.bf16.f32 " \
        "{%0,%1,%2,%3}, {%4,%5,%6,%7}, {%8,%9}, {%0,%1,%2,%3};" \
        : "+f"((d)[0]), "+f"((d)[1]), "+f"((d)[2]), "+f"((d)[3]) \
        : "r"(a0), "r"(a1), "r"(a2), "r"(a3), "r"(b0), "r"(b1))

// ---------------- bf16x3 mma.sync GEMM, packed hi/lo operands ---------------
// C[M, 128-tile of Ng] = epi(A @ B^T + bias); ~fp32 accuracy (hi*hi+hi*lo+lo*hi).
// BMT: 128 (8 warps 4x2, warp 32x64) or 64 (8 warps 2x4, warp 32x32).
// AMODE 0: row-major (M,K). 1: m -> wf[s=m>>2] slice (m&3)+1 (K=128).
//          2: kt<4 from A (row=128u32), kt>=4 from A2.
// RESID 0: none; 1: packed bf16 hi/lo; 2: fp32.
// 3-stage cp.async pipeline; pair-XOR smem swizzle.
template <int BMT, int AMODE, bool RELU, int RESID, bool RBCAST, bool BIAS2D,
          bool PERM, bool PACKOUT>
__global__ void __launch_bounds__(256, 2)
mma_gemm(int M, int Ng, int K,
         const uint32_t* __restrict__ A, const uint32_t* __restrict__ A2,
         const uint32_t* __restrict__ Bs,
         const float* __restrict__ bias, const void* __restrict__ resid,
         float* __restrict__ C) {
    extern __shared__ uint32_t smu[];
    constexpr int ASIZE = BMT * 32;            // u32 per A stage
    constexpr int SSTRIDE = ASIZE + 4096;      // + B stage (128x32 u32)
    constexpr int NI = (BMT == 128) ? 8 : 4;
    int tid = threadIdx.x;
    int lane = tid & 31, wid = tid >> 5;
    int wm = (BMT == 128) ? (wid & 3) : (wid & 1);
    int wn = (BMT == 128) ? (wid >> 2) : (wid >> 1);
    int m0 = blockIdx.y * BMT, n0 = blockIdx.x << 7;
    int nK = K >> 5;

    float acc[2][NI][4];
#pragma unroll
    for (int mi = 0; mi < 2; mi++)
#pragma unroll
        for (int ni = 0; ni < NI; ni++)
#pragma unroll
            for (int u = 0; u < 4; u++) acc[mi][ni][u] = 0.f;

    auto load_tile = [&](int kt) {
        uint32_t* dst = smu + (kt % 3) * SSTRIDE;
#pragma unroll
        for (int i = 0; i < BMT / 32; i++) {       // A tile BMT rows x 32 u32
            int c = tid + (i << 8);
            int row = c >> 3, j = c & 7;
            const uint32_t* g;
            if (AMODE == 0) {
                g = A + (size_t)(m0 + row) * K + (kt << 5) + (j << 2);
            } else if (AMODE == 1) {
                int m = m0 + row;
                g = A + (size_t)(m >> 2) * 640 + (((m & 3) + 1) << 7) + (kt << 5) + (j << 2);
            } else {
                const uint32_t* base = (kt < 4) ? A : A2;
                g = base + ((size_t)(m0 + row) << 7) + ((kt & 3) << 5) + (j << 2);
            }
            int ch = j ^ ((row & 3) << 1);
            uint32_t sa = smem_u32(dst + (row << 5) + (ch << 2));
            asm volatile("cp.async.cg.shared.global [%0], [%1], 16;"
                         :: "r"(sa), "l"(g) : "memory");
        }
#pragma unroll
        for (int i = 0; i < 4; i++) {              // B tile 128 rows x 32 u32
            int c = tid + (i << 8);
            int row = c >> 3, j = c & 7;
            const uint32_t* g = Bs + (size_t)(n0 + row) * K + (kt << 5) + (j << 2);
            int ch = j ^ ((row & 3) << 1);
            uint32_t sa = smem_u32(dst + ASIZE + (row << 5) + (ch << 2));
            asm volatile("cp.async.cg.shared.global [%0], [%1], 16;"
                         :: "r"(sa), "l"(g) : "memory");
        }
        asm volatile("cp.async.commit_group;" ::: "memory");
    };

    load_tile(0);
    load_tile(1);
    int g = lane >> 2, kc = lane & 3;
    int swz = (g & 3) << 2;
    int arow = wm * 32 + g;
    int brow = wn * ((BMT == 128) ? 64 : 32) + g;
    int o1v[2], o2v[2];
#pragma unroll
    for (int ks = 0; ks < 2; ks++) {
        o1v[ks] = 2 * ((ks * 8 + kc) ^ swz);
        o2v[ks] = 2 * ((ks * 8 + kc + 4) ^ swz);
    }

    for (int kt = 0; kt < nK; kt++) {
        if (kt + 2 < nK) {
            load_tile(kt + 2);
            asm volatile("cp.async.wait_group 2;" ::: "memory");
        } else if (kt + 1 < nK) {
            asm volatile("cp.async.wait_group 1;" ::: "memory");
        } else {
            asm volatile("cp.async.wait_group 0;" ::: "memory");
        }
        __syncthreads();
        const uint32_t* Asb = smu + (kt % 3) * SSTRIDE;
        const uint32_t* Bsb = Asb + ASIZE;
#pragma unroll
        for (int ks = 0; ks < 2; ks++) {
            int o1 = o1v[ks], o2 = o2v[ks];
            uint2 Af[2][4];
#pragma unroll
            for (int mi = 0; mi < 2; mi++) {
                const uint32_t* p = Asb + ((arow + mi * 16) << 5);
                Af[mi][0] = *(const uint2*)(p + o1);
                Af[mi][1] = *(const uint2*)(p + 256 + o1);    // +8 rows
                Af[mi][2] = *(const uint2*)(p + o2);
                Af[mi][3] = *(const uint2*)(p + 256 + o2);
            }
#pragma unroll
            for (int ni = 0; ni < NI; ni++) {
                const uint32_t* bp = Bsb + ((brow + ni * 8) << 5);
                uint2 B0 = *(const uint2*)(bp + o1);
                uint2 B1 = *(const uint2*)(bp + o2);
#pragma unroll
                for (int mi = 0; mi < 2; mi++) {
                    MMA_BF16(acc[mi][ni], Af[mi][0].x, Af[mi][1].x, Af[mi][2].x, Af[mi][3].x, B0.x, B1.x);
                    MMA_BF16(acc[mi][ni], Af[mi][0].x, Af[mi][1].x, Af[mi][2].x, Af[mi][3].x, B0.y, B1.y);
                    MMA_BF16(acc[mi][ni], Af[mi][0].y, Af[mi][1].y, Af[mi][2].y, Af[mi][3].y, B0.x, B1.x);
                }
            }
        }
        __syncthreads();
    }

    // Epilogue. c0:(g,2t) c1:(g,2t+1) c2:(g+8,2t) c3:(g+8,2t+1)
    int mrow = m0 + wm * 32 + g;
    int rsel = mrow & 3;
    int nc0 = n0 + wn * ((BMT == 128) ? 64 : 32) + 2 * kc;
    const uint32_t* Rp = (const uint32_t*)resid;
    const float* Rf = (const float*)resid;
#pragma unroll
    for (int ni = 0; ni < NI; ni++) {
        int n = nc0 + ni * 8;
        int boff = BIAS2D ? rsel * Ng : 0;
        float bv0 = bias[boff + n], bv1 = bias[boff + n + 1];
#pragma unroll
        for (int mi = 0; mi < 2; mi++) {
#pragma unroll
            for (int h2 = 0; h2 < 2; h2++) {
                int m = mrow + mi * 16 + h2 * 8;
                float x0 = acc[mi][ni][2 * h2]     + bv0;
                float x1 = acc[mi][ni][2 * h2 + 1] + bv1;
                if (RESID == 1) {
                    uint2 rv = *(const uint2*)(Rp + (size_t)m * Ng + n);
                    float2 rh = bf2_unpack(rv.x), rl = bf2_unpack(rv.y);
                    x0 += rh.x + rl.x;
                    x1 += rh.y + rl.y;
                } else if (RESID == 2) {
                    size_t rr = RBCAST ? ((size_t)(m >> 2) * Ng + n)
                                       : ((size_t)m * Ng + n);
                    x0 += Rf[rr];
                    x1 += Rf[rr + 1];
                }
                if (RELU) { x0 = fmaxf(x0, 0.f); x1 = fmaxf(x1, 0.f); }
                if (PERM) {
                    // m = (b*4096+pt)*4+r ; out idx = ((b*128+d)*4096+pt)*4+r
                    int bb = m >> 14;
                    size_t low = (size_t)(m & 16383);
                    C[(((size_t)(bb * 128 + n)) << 14) + low] = x0;
                    C[(((size_t)(bb * 128 + n + 1)) << 14) + low] = x1;
                } else if (PACKOUT) {
                    uint2 pw = pack_hilo(x0, x1);
                    *(uint2*)((uint32_t*)C + (size_t)m * Ng + n) = pw;
                } else {
                    *(float2*)(C + (size_t)m * Ng + n) = make_float2(x0, x1);
                }
            }
        }
    }
}

// -------- kernel-point correlation: packed feat0 -> packed wf --------------
__global__ void kp_wf_kernel(const float* __restrict__ pos,
                             const int* __restrict__ idx,
                             const float* __restrict__ qp,
                             const uint32_t* __restrict__ feat0,
                             uint32_t* __restrict__ wf) {
    int s = blockIdx.x;
    int b = s >> 12, n = s & (BQ_N - 1);
    int c = threadIdx.x;
    __shared__ float wsh[R1][KN];
    __shared__ int nidx[KN];
    if (c < KN) {
        int m = idx[(size_t)s * KN + c];
        nidx[c] = m;
        float wr[R1];
#pragma unroll
        for (int r = 0; r < R1; r++) wr[r] = 0.f;
        if (m < BQ_N) {
            const float* p = pos + (size_t)b * 3 * BQ_N;
            float rx = p[m] - p[n];
            float ry = p[BQ_N + m] - p[BQ_N + n];
            float rz = p[2 * BQ_N + m] - p[2 * BQ_N + n];
#pragma unroll
            for (int r = 0; r < R1; r++) {
                float dx = rx - qp[r];
                float dy = ry - qp[R1 + r];
                float dz = rz - qp[2 * R1 + r];
                float d = sqrtf(dx * dx + dy * dy + dz * dz);
                wr[r] = fmaxf(0.f, 1.f - d / 0.1f);
            }
        }
#pragma unroll
        for (int r = 0; r < R1; r++) wsh[r][c] = wr[r];
    }
    __syncthreads();
    float acc[R1] = {0.f, 0.f, 0.f, 0.f, 0.f};
    bool odd = (c & 1);
    int ce = c & ~1;
#pragma unroll 4
    for (int k = 0; k < KN; k++) {
        int m = nidx[k];
        float f = 0.f;
        if (m < BQ_N) {
            uint2 w = *(const uint2*)(feat0 + (((size_t)(b * BQ_N + m)) << 7) + ce);
            float2 hh = bf2_unpack(w.x), ll = bf2_unpack(w.y);
            f = odd ? (hh.y + ll.y) : (hh.x + ll.x);
        }
#pragma unroll
        for (int r = 0; r < R1; r++) acc[r] += wsh[r][k] * f;
    }
#pragma unroll
    for (int r = 0; r < R1; r++) {
        float v = acc[r];
        float vp = __shfl_xor_sync(0xffffffffu, v, 1);
        if (!odd) {
            uint2 pw = pack_hilo(v, vp);
            *(uint2*)(wf + (size_t)s * 640 + r * 128 + c) = pw;
        }
    }
}

// ---- setup: transpose(+pack) | ballquery | prep, by blockIdx range --------
#define T_BLOCKS 2048
#define B_BLOCKS 2048
#define PREP_TOTAL (8192 + 40960 + 8192 + 16384 + 32768 + 16384 + 1024 + 12)
#define P_BLOCKS ((PREP_TOTAL + 255) / 256)

__global__ void __launch_bounds__(256) setup_kernel(
    const float* __restrict__ feat, const float* __restrict__ pos,
    const float* __restrict__ w_begin, const float* __restrict__ kpw,
    const float* __restrict__ w_end, const float* __restrict__ w1,
    const float* __restrict__ w2, const float* __restrict__ qp,
    uint32_t* __restrict__ featT, int* __restrict__ idx,
    uint32_t* __restrict__ wbs, uint32_t* __restrict__ kpTs,
    uint32_t* __restrict__ wes, uint32_t* __restrict__ w1as,
    uint32_t* __restrict__ w1cds, uint32_t* __restrict__ m2s,
    float* __restrict__ bias2d, float* __restrict__ out12) {
    extern __shared__ float dynf[];   // 12288 floats (used by transpose + ballquery)
    int bid = blockIdx.x;
    int tid = threadIdx.x;
    if (bid < T_BLOCKS) {
        // ---- transpose feat (B,C,N) -> packed featT (B,N,C) ----
        float (*tile)[33] = (float (*)[33])dynf;
        int b = bid >> 9;
        int n0 = (bid & 127) * 32, c0 = ((bid >> 7) & 3) * 32;
        int tx = tid & 31, ty = tid >> 5;
#pragma unroll
        for (int i = ty; i < 32; i += 8)
            tile[i][tx] = feat[((size_t)(b * CC + c0 + i)) * BQ_N + n0 + tx];
        __syncthreads();
#pragma unroll
        for (int i = ty; i < 32; i += 8) {
            float v = tile[tx][i];
            float vp = __shfl_xor_sync(0xffffffffu, v, 1);
            if (!(tx & 1)) {
                uint2 pw = pack_hilo(v, vp);
                *(uint2*)(featT + (((size_t)(b * BQ_N + n0 + i)) << 7) + c0 + tx) = pw;
            }
        }
        return;
    }
    if (bid < T_BLOCKS + B_BLOCKS) {
        // ---- ball query: first 32 in-radius neighbors by index ----
        float* sx = dynf;
        float* sy = dynf + BQ_N;
        float* sz = dynf + 2 * BQ_N;
        int t = bid - T_BLOCKS;
        int b = t >> 9, bx = t & 511;
        const float* p = pos + (size_t)b * 3 * BQ_N;
        for (int i = tid; i < BQ_N; i += 256) {
            sx[i] = p[i];
            sy[i] = p[BQ_N + i];
            sz[i] = p[2 * BQ_N + i];
        }
        __syncthreads();
        int warp = tid >> 5, lane = tid & 31;
        int n = bx * 8 + warp;
        float xn = sx[n], yn = sy[n], zn = sz[n];
        float nn = xn * xn + yn * yn + zn * zn;
        int* out = idx + (size_t)(b * BQ_N + n) * KN;
        int count = 0;
        for (int m0 = 0; m0 < BQ_N && count < KN; m0 += 32) {
            int m = m0 + lane;
            float xm = sx[m], ym = sy[m], zm = sz[m];
            float nm = xm * xm + ym * ym + zm * zm;
            float dt = xn * xm + yn * ym + zn * zm;
            float sqd = (nn + nm) - 2.0f * dt;
            bool ok = (sqd <= CONV_R2);
            unsigned msk = __ballot_sync(0xffffffffu, ok);
            int p2 = count + __popc(msk & ((1u << lane) - 1u));
            if (ok && p2 < KN) out[p2] = m;
            count += __popc(msk);
            if (count > KN) count = KN;
        }
        for (int p2 = count + lane; p2 < KN; p2 += 32) out[p2] = BQ_N;
        return;
    }
    // ---- prep: pack weights hi/lo, bias2d, 12 query_pos outputs ----
    int t = (bid - T_BLOCKS - B_BLOCKS) * 256 + tid;
    if (t < 8192) {                              // w_begin (128,128): 64 pairs/row
        int o = t >> 6, p = t & 63;
        *(uint2*)(wbs + o * 128 + 2 * p) =
            pack_hilo(w_begin[o * 128 + 2 * p], w_begin[o * 128 + 2 * p + 1]);
        return;
    }
    t -= 8192;
    if (t < 40960) {                             // kpT (128,640): 320 pairs/row
        int c = t / 320, p = t % 320;
        *(uint2*)(kpTs + (size_t)c * 640 + 2 * p) =
            pack_hilo(kpw[(size_t)(2 * p) * 128 + c], kpw[(size_t)(2 * p + 1) * 128 + c]);
        return;
    }
    t -= 40960;
    if (t < 8192) {                              // w_end (128,128)
        int o = t >> 6, p = t & 63;
        *(uint2*)(wes + o * 128 + 2 * p) =
            pack_hilo(w_end[o * 128 + 2 * p], w_end[o * 128 + 2 * p + 1]);
        return;
    }
    t -= 8192;
    if (t < 16384) {                             // w1a (256,128): cols 0..127
        int o = t >> 6, p = t & 63;
        *(uint2*)(w1as + o * 128 + 2 * p) =
            pack_hilo(w1[(size_t)o * 387 + 2 * p], w1[(size_t)o * 387 + 2 * p + 1]);
        return;
    }
    t -= 16384;
    if (t < 32768) {                             // w1cd (256,256): cols 131..386
        int o = t >> 7, p = t & 127;
        *(uint2*)(w1cds + (size_t)o * 256 + 2 * p) =
            pack_hilo(w1[(size_t)o * 387 + 131 + 2 * p], w1[(size_t)o * 387 + 132 + 2 * p]);
        return;
    }
    t -= 32768;
    if (t < 16384) {                             // w_mlp2 (128,256)
        int o = t >> 7, p = t & 127;
        *(uint2*)(m2s + (size_t)o * 256 + 2 * p) =
            pack_hilo(w2[(size_t)o * 256 + 2 * p], w2[(size_t)o * 256 + 2 * p + 1]);
        return;
    }
    t -= 16384;
    if (t < 1024) {                              // bias2d[r][n] = sum_a W1[n][128+a]*qp[a][r+1]
        int r = t >> 8, n = t & 255;
        float s = 0.f;
#pragma unroll
        for (int a = 0; a < 3; a++)
            s += w1[(size_t)n * 387 + 128 + a] * qp[a * R1 + r + 1];
        bias2d[r * 256 + n] = s;
        return;
    }
    t -= 1024;
    if (t >= 0 && t < 12) {                      // query_pos output (3,4)
        int a = t >> 2, r = (t & 3) + 1;
        out12[t] = qp[a * R1 + r];
    }
}

// ---------------- launch ----------------------------------------------------
extern "C" void kernel_launch(void* const* d_in, const int* in_sizes, int n_in,
                              void* d_out, int out_size) {
    (void)in_sizes; (void)n_in; (void)out_size;
    const float* pos       = (const float*)d_in[0];
    const float* feat      = (const float*)d_in[1];
    const float* qp        = (const float*)d_in[2];
    const float* w_begin   = (const float*)d_in[3];
    const float* b_begin   = (const float*)d_in[4];
    const float* kp_weight = (const float*)d_in[5];
    const float* kp_bias   = (const float*)d_in[6];
    const float* w_end     = (const float*)d_in[7];
    const float* b_end     = (const float*)d_in[8];
    const float* w_mlp1    = (const float*)d_in[9];
    const float* b_mlp1    = (const float*)d_in[10];
    const float* w_mlp2    = (const float*)d_in[11];
    const float* b_mlp2    = (const float*)d_in[12];
    float* out = (float*)d_out;

    uint32_t *featT, *feat0, *wf, *qf, *qf2, *h;
    uint32_t *wbs, *kpTs, *wes, *w1as, *w1cds, *m2s;
    float *Y, *bias2d;
    int* idx;
    cudaGetSymbolAddress((void**)&featT, g_featT);
    cudaGetSymbolAddress((void**)&feat0, g_feat0);
    cudaGetSymbolAddress((void**)&idx,   g_idx);
    cudaGetSymbolAddress((void**)&wf,    g_wf);
    cudaGetSymbolAddress((void**)&qf,    g_qf);
    cudaGetSymbolAddress((void**)&qf2,   g_qf2);
    cudaGetSymbolAddress((void**)&Y,     g_Y);
    cudaGetSymbolAddress((void**)&h,     g_h);
    cudaGetSymbolAddress((void**)&wbs,   g_wbs);
    cudaGetSymbolAddress((void**)&kpTs,  g_kpTs);
    cudaGetSymbolAddress((void**)&wes,   g_wes);
    cudaGetSymbolAddress((void**)&w1as,  g_w1as);
    cudaGetSymbolAddress((void**)&w1cds, g_w1cds);
    cudaGetSymbolAddress((void**)&m2s,   g_m2s);
    cudaGetSymbolAddress((void**)&bias2d, g_bias2d);

    const int SMEM_SETUP = 3 * BQ_N * 4;            // 49152 B
    const int SMEM_S = 3 * (64 * 32 + 4096) * 4;    // 73728 B  (BMT=64)
    const int SMEM_B = 3 * (128 * 32 + 4096) * 4;   // 98304 B  (BMT=128)
    cudaFuncSetAttribute(setup_kernel,
                         cudaFuncAttributeMaxDynamicSharedMemorySize, SMEM_SETUP);
#define SETSM(SM, ...) cudaFuncSetAttribute(mma_gemm<__VA_ARGS__>, \
        cudaFuncAttributeMaxDynamicSharedMemorySize, SM)
    SETSM(SMEM_S, 64,  0, false, 0, false, false, false, true);
    SETSM(SMEM_S, 64,  0, true,  0, false, false, false, true);
    SETSM(SMEM_S, 64,  0, true,  1, false, false, false, true);
    SETSM(SMEM_S, 64,  2, false, 0, false, false, false, false);
    SETSM(SMEM_B, 128, 1, true,  2, true,  true,  false, true);
    SETSM(SMEM_B, 128, 0, true,  0, false, false, true,  false);
#undef SETSM

    // Stage 0: fused transpose + ball query + prep
    setup_kernel<<<T_BLOCKS + B_BLOCKS + P_BLOCKS, 256, SMEM_SETUP>>>(
        feat, pos, w_begin, kp_weight, w_end, w_mlp1, w_mlp2, qp,
        featT, idx, wbs, kpTs, wes, w1as, w1cds, m2s, bias2d, out);

    // feat0 = featT @ w_begin^T + b_begin          (packed out)
    mma_gemm<64, 0, false, 0, false, false, false, true><<<dim3(1, 256), 256, SMEM_S>>>(
        S_TOT, 128, 128, featT, nullptr, wbs, b_begin, nullptr, (float*)feat0);

    // kernel-point correlation -> wf (S, 640)      (packed out)
    kp_wf_kernel<<<S_TOT, 128>>>(pos, idx, qp, feat0, wf);

    // qf = relu(wf @ kpT^T + kp_bias)              (packed out)
    mma_gemm<64, 0, true, 0, false, false, false, true><<<dim3(1, 256), 256, SMEM_S>>>(
        S_TOT, 128, 640, wf, nullptr, kpTs, kp_bias, nullptr, (float*)qf);

    // qf2 = relu(qf @ w_end^T + b_end + featT)     (packed resid, packed out)
    mma_gemm<64, 0, true, 1, false, false, false, true><<<dim3(1, 256), 256, SMEM_S>>>(
        S_TOT, 128, 128, qf, nullptr, wes, b_end, featT, (float*)qf2);

    // Y = [qf2 | featT] @ w1cd^T + b_mlp1          (fp32 out; resid for h)
    mma_gemm<64, 2, false, 0, false, false, false, false><<<dim3(2, 256), 256, SMEM_S>>>(
        S_TOT, 256, 256, qf2, featT, w1cds, b_mlp1, nullptr, Y);

    // h = relu(wf_r @ w1a^T + bias2d[r] + Y[s])    (packed out)
    mma_gemm<128, 1, true, 2, true, true, false, true><<<dim3(2, 512), 256, SMEM_B>>>(
        S2_TOT, 256, 128, wf, nullptr, w1as, bias2d, Y, (float*)h);

    // queries = relu(h @ w_mlp2^T + b_mlp2), scattered to (B, TD, N, R)
    mma_gemm<128, 0, true, 0, false, false, true, false><<<dim3(1, 512), 256, SMEM_B>>>(
        S2_TOT, 128, 256, h, nullptr, m2s, b_mlp2, nullptr, out + 12);
}